// round 3
// baseline (speedup 1.0000x reference)
#include <cuda_runtime.h>
#include <math.h>

#define S_LEN  2048
#define B_SZ   2
#define DMODEL 4096
#define KVDIM  1024
#define HD     128
#define NH     32
#define NKV    8

// ---------------- scratch (static device globals; no allocation) ----------------
__device__ float g_q[(size_t)B_SZ * NH  * S_LEN * HD];   // [b][h][s][d]
__device__ float g_k[(size_t)B_SZ * NKV * S_LEN * HD];   // [b][g][s][d]
__device__ float g_v[(size_t)B_SZ * NKV * S_LEN * HD];   // [b][g][s][d]
__device__ float g_attn[(size_t)B_SZ * S_LEN * DMODEL];  // [b*s][h*128+d]

// ---------------- GEMM: 128x128 tile, K-step 16, 256 threads, 8x8/thread -------
// mode 1: A = x, fused QKV (W0=wq, W1=wk, W2=wv), scatter epilogue into g_q/g_k/g_v
// mode 2: A = g_attn (internal), C = A @ W0 plain row-major store
__global__ __launch_bounds__(256) void gemm_kernel(
    const float* __restrict__ A_in, int K, int mode,
    const float* __restrict__ W0, const float* __restrict__ W1,
    const float* __restrict__ W2, float* __restrict__ C, int ldc)
{
    __shared__ float As[16][132];   // transposed A tile: As[k][m]
    __shared__ float Bs[16][132];   // Bs[k][n]

    const float* A = (mode == 2) ? g_attn : A_in;

    const int t  = threadIdx.x;
    const int m0 = blockIdx.y * 128;
    const int n0 = blockIdx.x * 128;

    const float* Bp; int ldb; int bc;
    if (mode == 2)                  { Bp = W0; ldb = ldc;   bc = n0; }
    else if (n0 < DMODEL)           { Bp = W0; ldb = DMODEL; bc = n0; }
    else if (n0 < DMODEL + KVDIM)   { Bp = W1; ldb = KVDIM;  bc = n0 - DMODEL; }
    else                            { Bp = W2; ldb = KVDIM;  bc = n0 - DMODEL - KVDIM; }

    const int arow = t >> 2;           // 0..63
    const int acol = (t & 3) << 2;     // 0,4,8,12
    const int brow = t >> 5;           // 0..7
    const int bcol = (t & 31) << 2;    // 0..124

    const float* Ap  = A  + (size_t)(m0 + arow) * K + acol;
    const float* Bpp = Bp + (size_t)brow * ldb + bc + bcol;

    const int ty = t >> 4, tx = t & 15;
    float acc[8][8];
#pragma unroll
    for (int i = 0; i < 8; i++)
#pragma unroll
        for (int j = 0; j < 8; j++) acc[i][j] = 0.f;

    for (int k0 = 0; k0 < K; k0 += 16) {
        float4 a0 = *(const float4*)Ap;
        float4 a1 = *(const float4*)(Ap + (size_t)64 * K);
        float4 b0 = *(const float4*)Bpp;
        float4 b1 = *(const float4*)(Bpp + (size_t)8 * ldb);

        As[acol + 0][arow] = a0.x;  As[acol + 1][arow] = a0.y;
        As[acol + 2][arow] = a0.z;  As[acol + 3][arow] = a0.w;
        As[acol + 0][arow + 64] = a1.x;  As[acol + 1][arow + 64] = a1.y;
        As[acol + 2][arow + 64] = a1.z;  As[acol + 3][arow + 64] = a1.w;
        *(float4*)&Bs[brow][bcol]     = b0;
        *(float4*)&Bs[brow + 8][bcol] = b1;
        __syncthreads();

#pragma unroll
        for (int kk = 0; kk < 16; kk++) {
            float ar[8], br[8];
            *(float4*)&ar[0] = *(const float4*)&As[kk][ty * 8];
            *(float4*)&ar[4] = *(const float4*)&As[kk][ty * 8 + 4];
            *(float4*)&br[0] = *(const float4*)&Bs[kk][tx * 8];
            *(float4*)&br[4] = *(const float4*)&Bs[kk][tx * 8 + 4];
#pragma unroll
            for (int i = 0; i < 8; i++)
#pragma unroll
                for (int j = 0; j < 8; j++)
                    acc[i][j] = fmaf(ar[i], br[j], acc[i][j]);
        }
        __syncthreads();
        Ap  += 16;
        Bpp += (size_t)16 * ldb;
    }

    if (mode == 2) {
#pragma unroll
        for (int i = 0; i < 8; i++) {
            float* cp = C + (size_t)(m0 + ty * 8 + i) * ldc + n0 + tx * 8;
            *(float4*)cp       = make_float4(acc[i][0], acc[i][1], acc[i][2], acc[i][3]);
            *(float4*)(cp + 4) = make_float4(acc[i][4], acc[i][5], acc[i][6], acc[i][7]);
        }
    } else {
        // each 128-wide n-block is exactly one head; each 128-tall m-block stays in one batch
        const int b    = m0 >> 11;        // m0 / 2048
        const int srow = m0 & (S_LEN - 1);
        float* dst;
        if (n0 < DMODEL)
            dst = g_q + ((size_t)(b * NH  + (n0 >> 7)) * S_LEN + srow) * HD;
        else if (n0 < DMODEL + KVDIM)
            dst = g_k + ((size_t)(b * NKV + ((n0 - DMODEL) >> 7)) * S_LEN + srow) * HD;
        else
            dst = g_v + ((size_t)(b * NKV + ((n0 - DMODEL - KVDIM) >> 7)) * S_LEN + srow) * HD;
#pragma unroll
        for (int i = 0; i < 8; i++) {
            float* cp = dst + (size_t)(ty * 8 + i) * HD + tx * 8;
            *(float4*)cp       = make_float4(acc[i][0], acc[i][1], acc[i][2], acc[i][3]);
            *(float4*)(cp + 4) = make_float4(acc[i][4], acc[i][5], acc[i][6], acc[i][7]);
        }
    }
}

// ---------------- RoPE (in-place on g_q / g_k) ----------------------------------
__global__ void rope_kernel(int which, int total,
                            const float* __restrict__ cs, const float* __restrict__ sn)
{
    int idx = blockIdx.x * blockDim.x + threadIdx.x;
    if (idx >= total) return;
    float* xp = which ? g_k : g_q;
    int j = idx & 63;
    int s = (idx >> 6) & (S_LEN - 1);
    float c  = cs[s * 64 + j];
    float si = sn[s * 64 + j];
    float2 v = *(float2*)(xp + (size_t)idx * 2);
    float2 o;
    o.x = v.x * c - v.y * si;
    o.y = v.x * si + v.y * c;
    *(float2*)(xp + (size_t)idx * 2) = o;
}

// ---------------- flash attention: BQ=64, BK=64, full (non-causal) softmax ------
// grid: (S/64, B*NH), 256 threads. smem: Qt[128][68] + KV(max 128*68) + P[64][68]
#define ATTN_SMEM ((128 * 68 + 128 * 68 + 64 * 68) * 4)

__global__ __launch_bounds__(256) void attn_kernel()
{
    extern __shared__ float sm[];
    float* sQ  = sm;                 // Q transposed: sQ[d*68 + r], pre-scaled
    float* sKV = sm + 128 * 68;      // K transposed (d*68+c) then V natural (kk*128+d)
    float* sP  = sm + 2 * 128 * 68;  // probs: sP[r*68 + c]

    const int t  = threadIdx.x;
    const int qt = blockIdx.x;       // q tile 0..31
    const int bh = blockIdx.y;       // 0..63
    const int b  = bh >> 5;
    const int h  = bh & 31;
    const int g  = h >> 2;           // kv head

    const float* qbase = g_q + ((size_t)bh * S_LEN + qt * 64) * HD;
    const float* kbase = g_k + (size_t)(b * NKV + g) * S_LEN * HD;
    const float* vbase = g_v + (size_t)(b * NKV + g) * S_LEN * HD;

    const float scale = 0.08838834764831845f;  // 1/sqrt(128)

    // load Q tile transposed, folded scale
#pragma unroll
    for (int i = 0; i < 32; i++) {
        int idx = t + i * 256;               // 0..8191
        sQ[(idx & 127) * 68 + (idx >> 7)] = qbase[idx] * scale;
    }

    const int ty = t >> 4, tx = t & 15;
    const int r0 = ty * 4, c0 = tx * 4, oc0 = tx * 8;

    float m_i[4], l_i[4], o[4][8];
#pragma unroll
    for (int i = 0; i < 4; i++) {
        m_i[i] = -1e30f; l_i[i] = 0.f;
#pragma unroll
        for (int j = 0; j < 8; j++) o[i][j] = 0.f;
    }

    for (int kt = 0; kt < S_LEN / 64; kt++) {
        __syncthreads();  // prev PV done (and Q ready on iter 0)

        // load K tile transposed
        const float* kp = kbase + (size_t)kt * 64 * HD;
#pragma unroll
        for (int i = 0; i < 32; i++) {
            int idx = t + i * 256;
            sKV[(idx & 127) * 68 + (idx >> 7)] = kp[idx];
        }
        __syncthreads();

        // S = Q K^T (4x4 per thread)
        float s[4][4];
#pragma unroll
        for (int i = 0; i < 4; i++)
#pragma unroll
            for (int j = 0; j < 4; j++) s[i][j] = 0.f;

#pragma unroll 8
        for (int d = 0; d < 128; d++) {
            float4 a  = *(const float4*)&sQ [d * 68 + r0];
            float4 bb = *(const float4*)&sKV[d * 68 + c0];
            float av[4] = {a.x, a.y, a.z, a.w};
            float bv[4] = {bb.x, bb.y, bb.z, bb.w};
#pragma unroll
            for (int i = 0; i < 4; i++)
#pragma unroll
                for (int j = 0; j < 4; j++)
                    s[i][j] = fmaf(av[i], bv[j], s[i][j]);
        }

        // online softmax (rows shared by the 16 tx lanes -> shfl reduce)
        float alpha[4];
#pragma unroll
        for (int i = 0; i < 4; i++) {
            float mx = fmaxf(fmaxf(s[i][0], s[i][1]), fmaxf(s[i][2], s[i][3]));
#pragma unroll
            for (int off = 8; off > 0; off >>= 1)
                mx = fmaxf(mx, __shfl_xor_sync(0xffffffffu, mx, off));
            float mnew = fmaxf(m_i[i], mx);
            float al   = __expf(m_i[i] - mnew);
            m_i[i] = mnew;
            float sum = 0.f;
#pragma unroll
            for (int j = 0; j < 4; j++) { s[i][j] = __expf(s[i][j] - mnew); sum += s[i][j]; }
#pragma unroll
            for (int off = 8; off > 0; off >>= 1)
                sum += __shfl_xor_sync(0xffffffffu, sum, off);
            l_i[i] = l_i[i] * al + sum;
            alpha[i] = al;
        }

        // stash probs
#pragma unroll
        for (int i = 0; i < 4; i++)
#pragma unroll
            for (int j = 0; j < 4; j++)
                sP[(r0 + i) * 68 + c0 + j] = s[i][j];
        __syncthreads();  // done reading K-tile + all P written

        // load V tile (natural layout) into same buffer
        const float* vp = vbase + (size_t)kt * 64 * HD;
#pragma unroll
        for (int i = 0; i < 32; i++) {
            int idx = t + i * 256;
            sKV[idx] = vp[idx];
        }
        __syncthreads();

        // rescale + O += P V
#pragma unroll
        for (int i = 0; i < 4; i++) {
            float al = alpha[i];
#pragma unroll
            for (int j = 0; j < 8; j++) o[i][j] *= al;
        }
#pragma unroll 4
        for (int kk = 0; kk < 64; kk++) {
            float4 v0 = *(const float4*)&sKV[kk * 128 + oc0];
            float4 v1 = *(const float4*)&sKV[kk * 128 + oc0 + 4];
            float vv[8] = {v0.x, v0.y, v0.z, v0.w, v1.x, v1.y, v1.z, v1.w};
#pragma unroll
            for (int i = 0; i < 4; i++) {
                float p = sP[(r0 + i) * 68 + kk];
#pragma unroll
                for (int j = 0; j < 8; j++)
                    o[i][j] = fmaf(p, vv[j], o[i][j]);
            }
        }
    }

    // normalize + write to g_attn [b*s][h*128+d]
#pragma unroll
    for (int i = 0; i < 4; i++) {
        float inv = 1.f / l_i[i];
        int srow  = qt * 64 + r0 + i;
        float* op = g_attn + ((size_t)(b * S_LEN + srow)) * DMODEL + h * HD + oc0;
        *(float4*)op       = make_float4(o[i][0] * inv, o[i][1] * inv, o[i][2] * inv, o[i][3] * inv);
        *(float4*)(op + 4) = make_float4(o[i][4] * inv, o[i][5] * inv, o[i][6] * inv, o[i][7] * inv);
    }
}

// ---------------- launch ---------------------------------------------------------
extern "C" void kernel_launch(void* const* d_in, const int* in_sizes, int n_in,
                              void* d_out, int out_size)
{
    const float* x  = (const float*)d_in[0];
    const float* cs = (const float*)d_in[1];
    const float* sn = (const float*)d_in[2];
    const float* wq = (const float*)d_in[3];
    const float* wk = (const float*)d_in[4];
    const float* wv = (const float*)d_in[5];
    const float* wo = (const float*)d_in[6];
    // d_in[7] = start_pos (always 0 for this problem)
    float* out = (float*)d_out;

    cudaFuncSetAttribute(attn_kernel, cudaFuncAttributeMaxDynamicSharedMemorySize, ATTN_SMEM);

    // 1) fused QKV projection + scatter to [b][h][s][d] scratch
    gemm_kernel<<<dim3((DMODEL + 2 * KVDIM) / 128, (B_SZ * S_LEN) / 128), 256>>>(
        x, DMODEL, 1, wq, wk, wv, nullptr, 0);

    // 2) RoPE on Q and K
    rope_kernel<<<(B_SZ * NH * S_LEN * 64) / 256, 256>>>(0, B_SZ * NH * S_LEN * 64, cs, sn);
    rope_kernel<<<(B_SZ * NKV * S_LEN * 64) / 256, 256>>>(1, B_SZ * NKV * S_LEN * 64, cs, sn);

    // 3) attention
    attn_kernel<<<dim3(S_LEN / 64, B_SZ * NH), 256, ATTN_SMEM>>>();

    // 4) output projection (A = g_attn picked up inside the kernel)
    gemm_kernel<<<dim3(DMODEL / 128, (B_SZ * S_LEN) / 128), 256>>>(
        nullptr, DMODEL, 2, wo, nullptr, nullptr, out, DMODEL);
}

// round 4
// speedup vs baseline: 1.6294x; 1.6294x over previous
#include <cuda_runtime.h>
#include <math.h>

#define S_LEN  2048
#define B_SZ   2
#define DMODEL 4096
#define KVDIM  1024
#define HD     128
#define NH     32
#define NKV    8

// ---------------- scratch (static device globals; no allocation) ----------------
__device__ float g_q[(size_t)B_SZ * NH  * S_LEN * HD];   // [b][h][s][d]
__device__ float g_k[(size_t)B_SZ * NKV * S_LEN * HD];   // [b][g][s][d]
__device__ float g_v[(size_t)B_SZ * NKV * S_LEN * HD];   // [b][g][s][d]
__device__ float g_attn[(size_t)B_SZ * S_LEN * DMODEL];  // [b*s][h*128+d]

// ---------------- GEMM: 128x128 tile, K-step 16, 256 threads, 8x8/thread -------
// mode 1: A = x, fused QKV (W0=wq, W1=wk, W2=wv), scatter epilogue into g_q/g_k/g_v
// mode 2: A = g_attn (internal), C = A @ W0 plain row-major store
__global__ __launch_bounds__(256) void gemm_kernel(
    const float* __restrict__ A_in, int K, int mode,
    const float* __restrict__ W0, const float* __restrict__ W1,
    const float* __restrict__ W2, float* __restrict__ C, int ldc)
{
    __shared__ float As[16][132];   // transposed A tile: As[k][m]
    __shared__ float Bs[16][132];   // Bs[k][n]

    const float* A = (mode == 2) ? g_attn : A_in;

    const int t  = threadIdx.x;
    const int m0 = blockIdx.y * 128;
    const int n0 = blockIdx.x * 128;

    const float* Bp; int ldb; int bc;
    if (mode == 2)                  { Bp = W0; ldb = ldc;   bc = n0; }
    else if (n0 < DMODEL)           { Bp = W0; ldb = DMODEL; bc = n0; }
    else if (n0 < DMODEL + KVDIM)   { Bp = W1; ldb = KVDIM;  bc = n0 - DMODEL; }
    else                            { Bp = W2; ldb = KVDIM;  bc = n0 - DMODEL - KVDIM; }

    const int arow = t >> 2;           // 0..63
    const int acol = (t & 3) << 2;     // 0,4,8,12
    const int brow = t >> 5;           // 0..7
    const int bcol = (t & 31) << 2;    // 0..124

    const float* Ap  = A  + (size_t)(m0 + arow) * K + acol;
    const float* Bpp = Bp + (size_t)brow * ldb + bc + bcol;

    const int ty = t >> 4, tx = t & 15;
    float acc[8][8];
#pragma unroll
    for (int i = 0; i < 8; i++)
#pragma unroll
        for (int j = 0; j < 8; j++) acc[i][j] = 0.f;

    for (int k0 = 0; k0 < K; k0 += 16) {
        float4 a0 = *(const float4*)Ap;
        float4 a1 = *(const float4*)(Ap + (size_t)64 * K);
        float4 b0 = *(const float4*)Bpp;
        float4 b1 = *(const float4*)(Bpp + (size_t)8 * ldb);

        As[acol + 0][arow] = a0.x;  As[acol + 1][arow] = a0.y;
        As[acol + 2][arow] = a0.z;  As[acol + 3][arow] = a0.w;
        As[acol + 0][arow + 64] = a1.x;  As[acol + 1][arow + 64] = a1.y;
        As[acol + 2][arow + 64] = a1.z;  As[acol + 3][arow + 64] = a1.w;
        *(float4*)&Bs[brow][bcol]     = b0;
        *(float4*)&Bs[brow + 8][bcol] = b1;
        __syncthreads();

#pragma unroll
        for (int kk = 0; kk < 16; kk++) {
            float ar[8], br[8];
            *(float4*)&ar[0] = *(const float4*)&As[kk][ty * 8];
            *(float4*)&ar[4] = *(const float4*)&As[kk][ty * 8 + 4];
            *(float4*)&br[0] = *(const float4*)&Bs[kk][tx * 8];
            *(float4*)&br[4] = *(const float4*)&Bs[kk][tx * 8 + 4];
#pragma unroll
            for (int i = 0; i < 8; i++)
#pragma unroll
                for (int j = 0; j < 8; j++)
                    acc[i][j] = fmaf(ar[i], br[j], acc[i][j]);
        }
        __syncthreads();
        Ap  += 16;
        Bpp += (size_t)16 * ldb;
    }

    if (mode == 2) {
#pragma unroll
        for (int i = 0; i < 8; i++) {
            float* cp = C + (size_t)(m0 + ty * 8 + i) * ldc + n0 + tx * 8;
            *(float4*)cp       = make_float4(acc[i][0], acc[i][1], acc[i][2], acc[i][3]);
            *(float4*)(cp + 4) = make_float4(acc[i][4], acc[i][5], acc[i][6], acc[i][7]);
        }
    } else {
        // each 128-wide n-block is exactly one head; each 128-tall m-block stays in one batch
        const int b    = m0 >> 11;        // m0 / 2048
        const int srow = m0 & (S_LEN - 1);
        float* dst;
        if (n0 < DMODEL)
            dst = g_q + ((size_t)(b * NH  + (n0 >> 7)) * S_LEN + srow) * HD;
        else if (n0 < DMODEL + KVDIM)
            dst = g_k + ((size_t)(b * NKV + ((n0 - DMODEL) >> 7)) * S_LEN + srow) * HD;
        else
            dst = g_v + ((size_t)(b * NKV + ((n0 - DMODEL - KVDIM) >> 7)) * S_LEN + srow) * HD;
#pragma unroll
        for (int i = 0; i < 8; i++) {
            float* cp = dst + (size_t)(ty * 8 + i) * HD + tx * 8;
            *(float4*)cp       = make_float4(acc[i][0], acc[i][1], acc[i][2], acc[i][3]);
            *(float4*)(cp + 4) = make_float4(acc[i][4], acc[i][5], acc[i][6], acc[i][7]);
        }
    }
}

// ---------------- RoPE (in-place on g_q / g_k) ----------------------------------
__global__ void rope_kernel(int which, int total,
                            const float* __restrict__ cs, const float* __restrict__ sn)
{
    int idx = blockIdx.x * blockDim.x + threadIdx.x;
    if (idx >= total) return;
    float* xp = which ? g_k : g_q;
    int j = idx & 63;
    int s = (idx >> 6) & (S_LEN - 1);
    float c  = cs[s * 64 + j];
    float si = sn[s * 64 + j];
    float2 v = *(float2*)(xp + (size_t)idx * 2);
    float2 o;
    o.x = v.x * c - v.y * si;
    o.y = v.x * si + v.y * c;
    *(float2*)(xp + (size_t)idx * 2) = o;
}

// ---------------- flash attention: BQ=64, BK=64, full (non-causal) softmax ------
// grid: (S/64, B*NH), 256 threads. smem: Qt[128][68] + KV(max 128*68) + P[64][68]
#define ATTN_SMEM ((128 * 68 + 128 * 68 + 64 * 68) * 4)

__global__ __launch_bounds__(256) void attn_kernel()
{
    extern __shared__ float sm[];
    float* sQ  = sm;                 // Q transposed: sQ[d*68 + r], pre-scaled
    float* sKV = sm + 128 * 68;      // K transposed (d*68+c) then V natural (kk*128+d)
    float* sP  = sm + 2 * 128 * 68;  // probs: sP[r*68 + c]

    const int t  = threadIdx.x;
    const int qt = blockIdx.x;       // q tile 0..31
    const int bh = blockIdx.y;       // 0..63
    const int b  = bh >> 5;
    const int h  = bh & 31;
    const int g  = h >> 2;           // kv head

    const float* qbase = g_q + ((size_t)bh * S_LEN + qt * 64) * HD;
    const float* kbase = g_k + (size_t)(b * NKV + g) * S_LEN * HD;
    const float* vbase = g_v + (size_t)(b * NKV + g) * S_LEN * HD;

    const float scale = 0.08838834764831845f;  // 1/sqrt(128)

    // load Q tile transposed, folded scale
#pragma unroll
    for (int i = 0; i < 32; i++) {
        int idx = t + i * 256;               // 0..8191
        sQ[(idx & 127) * 68 + (idx >> 7)] = qbase[idx] * scale;
    }

    const int ty = t >> 4, tx = t & 15;
    const int r0 = ty * 4, c0 = tx * 4, oc0 = tx * 8;

    float m_i[4], l_i[4], o[4][8];
#pragma unroll
    for (int i = 0; i < 4; i++) {
        m_i[i] = -1e30f; l_i[i] = 0.f;
#pragma unroll
        for (int j = 0; j < 8; j++) o[i][j] = 0.f;
    }

    for (int kt = 0; kt < S_LEN / 64; kt++) {
        __syncthreads();  // prev PV done (and Q ready on iter 0)

        // load K tile transposed
        const float* kp = kbase + (size_t)kt * 64 * HD;
#pragma unroll
        for (int i = 0; i < 32; i++) {
            int idx = t + i * 256;
            sKV[(idx & 127) * 68 + (idx >> 7)] = kp[idx];
        }
        __syncthreads();

        // S = Q K^T (4x4 per thread)
        float s[4][4];
#pragma unroll
        for (int i = 0; i < 4; i++)
#pragma unroll
            for (int j = 0; j < 4; j++) s[i][j] = 0.f;

#pragma unroll 8
        for (int d = 0; d < 128; d++) {
            float4 a  = *(const float4*)&sQ [d * 68 + r0];
            float4 bb = *(const float4*)&sKV[d * 68 + c0];
            float av[4] = {a.x, a.y, a.z, a.w};
            float bv[4] = {bb.x, bb.y, bb.z, bb.w};
#pragma unroll
            for (int i = 0; i < 4; i++)
#pragma unroll
                for (int j = 0; j < 4; j++)
                    s[i][j] = fmaf(av[i], bv[j], s[i][j]);
        }

        // online softmax (rows shared by the 16 tx lanes -> shfl reduce)
        float alpha[4];
#pragma unroll
        for (int i = 0; i < 4; i++) {
            float mx = fmaxf(fmaxf(s[i][0], s[i][1]), fmaxf(s[i][2], s[i][3]));
#pragma unroll
            for (int off = 8; off > 0; off >>= 1)
                mx = fmaxf(mx, __shfl_xor_sync(0xffffffffu, mx, off));
            float mnew = fmaxf(m_i[i], mx);
            float al   = __expf(m_i[i] - mnew);
            m_i[i] = mnew;
            float sum = 0.f;
#pragma unroll
            for (int j = 0; j < 4; j++) { s[i][j] = __expf(s[i][j] - mnew); sum += s[i][j]; }
#pragma unroll
            for (int off = 8; off > 0; off >>= 1)
                sum += __shfl_xor_sync(0xffffffffu, sum, off);
            l_i[i] = l_i[i] * al + sum;
            alpha[i] = al;
        }

        // stash probs
#pragma unroll
        for (int i = 0; i < 4; i++)
#pragma unroll
            for (int j = 0; j < 4; j++)
                sP[(r0 + i) * 68 + c0 + j] = s[i][j];
        __syncthreads();  // done reading K-tile + all P written

        // load V tile (natural layout) into same buffer
        const float* vp = vbase + (size_t)kt * 64 * HD;
#pragma unroll
        for (int i = 0; i < 32; i++) {
            int idx = t + i * 256;
            sKV[idx] = vp[idx];
        }
        __syncthreads();

        // rescale + O += P V
#pragma unroll
        for (int i = 0; i < 4; i++) {
            float al = alpha[i];
#pragma unroll
            for (int j = 0; j < 8; j++) o[i][j] *= al;
        }
#pragma unroll 4
        for (int kk = 0; kk < 64; kk++) {
            float4 v0 = *(const float4*)&sKV[kk * 128 + oc0];
            float4 v1 = *(const float4*)&sKV[kk * 128 + oc0 + 4];
            float vv[8] = {v0.x, v0.y, v0.z, v0.w, v1.x, v1.y, v1.z, v1.w};
#pragma unroll
            for (int i = 0; i < 4; i++) {
                float p = sP[(r0 + i) * 68 + kk];
#pragma unroll
                for (int j = 0; j < 8; j++)
                    o[i][j] = fmaf(p, vv[j], o[i][j]);
            }
        }
    }

    // normalize + write to g_attn [b*s][h*128+d]
#pragma unroll
    for (int i = 0; i < 4; i++) {
        float inv = 1.f / l_i[i];
        int srow  = qt * 64 + r0 + i;
        float* op = g_attn + ((size_t)(b * S_LEN + srow)) * DMODEL + h * HD + oc0;
        *(float4*)op       = make_float4(o[i][0] * inv, o[i][1] * inv, o[i][2] * inv, o[i][3] * inv);
        *(float4*)(op + 4) = make_float4(o[i][4] * inv, o[i][5] * inv, o[i][6] * inv, o[i][7] * inv);
    }
}

// ---------------- launch ---------------------------------------------------------
extern "C" void kernel_launch(void* const* d_in, const int* in_sizes, int n_in,
                              void* d_out, int out_size)
{
    const float* x  = (const float*)d_in[0];
    const float* cs = (const float*)d_in[1];
    const float* sn = (const float*)d_in[2];
    const float* wq = (const float*)d_in[3];
    const float* wk = (const float*)d_in[4];
    const float* wv = (const float*)d_in[5];
    const float* wo = (const float*)d_in[6];
    // d_in[7] = start_pos (always 0 for this problem)
    float* out = (float*)d_out;

    cudaFuncSetAttribute(attn_kernel, cudaFuncAttributeMaxDynamicSharedMemorySize, ATTN_SMEM);

    // 1) fused QKV projection + scatter to [b][h][s][d] scratch
    gemm_kernel<<<dim3((DMODEL + 2 * KVDIM) / 128, (B_SZ * S_LEN) / 128), 256>>>(
        x, DMODEL, 1, wq, wk, wv, nullptr, 0);

    // 2) RoPE on Q and K
    rope_kernel<<<(B_SZ * NH * S_LEN * 64) / 256, 256>>>(0, B_SZ * NH * S_LEN * 64, cs, sn);
    rope_kernel<<<(B_SZ * NKV * S_LEN * 64) / 256, 256>>>(1, B_SZ * NKV * S_LEN * 64, cs, sn);

    // 3) attention
    attn_kernel<<<dim3(S_LEN / 64, B_SZ * NH), 256, ATTN_SMEM>>>();

    // 4) output projection (A = g_attn picked up inside the kernel)
    gemm_kernel<<<dim3(DMODEL / 128, (B_SZ * S_LEN) / 128), 256>>>(
        nullptr, DMODEL, 2, wo, nullptr, nullptr, out, DMODEL);
}

// round 5
// speedup vs baseline: 2.9694x; 1.8223x over previous
#include <cuda_runtime.h>
#include <math.h>

#define S_LEN  2048
#define B_SZ   2
#define DMODEL 4096
#define KVDIM  1024
#define HD     128
#define NH     32
#define NKV    8

// ---------------- scratch (static device globals; no allocation) ----------------
__device__ float g_q[(size_t)B_SZ * NH  * S_LEN * HD];   // [b][h][s][d]
__device__ float g_k[(size_t)B_SZ * NKV * S_LEN * HD];   // [b][g][s][d]
__device__ float g_v[(size_t)B_SZ * NKV * S_LEN * HD];   // [b][g][s][d]
__device__ float g_attn[(size_t)B_SZ * S_LEN * DMODEL];  // [b*s][h*128+d]

// ================= TF32 tensor-core GEMM =========================================
// 128x128 CTA tile, BK=16, 256 threads = 8 warps as 4(m) x 2(n), warp tile 32x64.
// mma.sync.m16n8k8 tf32, fp32 accumulate. cp.async double-buffered smem.
// mode 1: A = x, fused QKV (W0=wq,W1=wk,W2=wv), epilogue scatters to g_q/g_k/g_v
//         with RoPE fused for Q and K heads.
// mode 2: A = g_attn, C = A @ W0, plain row-major store.

#define BM 128
#define BN 128
#define BK 16
#define ASTR 20    // A smem row stride (floats): [m][k], frag gather conflict-free
#define BSTR 136   // B smem row stride (floats): [k][n], frag gather conflict-free

__device__ __forceinline__ unsigned f2tf(float f) {
    unsigned u;
    asm("cvt.rna.tf32.f32 %0, %1;" : "=r"(u) : "f"(f));
    return u;
}

__device__ __forceinline__ void mma_tf32(float c[4],
    unsigned a0, unsigned a1, unsigned a2, unsigned a3,
    unsigned b0, unsigned b1)
{
    asm volatile(
        "mma.sync.aligned.m16n8k8.row.col.f32.tf32.tf32.f32 "
        "{%0,%1,%2,%3}, {%4,%5,%6,%7}, {%8,%9}, {%0,%1,%2,%3};"
        : "+f"(c[0]), "+f"(c[1]), "+f"(c[2]), "+f"(c[3])
        : "r"(a0), "r"(a1), "r"(a2), "r"(a3), "r"(b0), "r"(b1));
}

__device__ __forceinline__ void cpa16(float* smem_dst, const float* gsrc) {
    unsigned s = (unsigned)__cvta_generic_to_shared(smem_dst);
    asm volatile("cp.async.cg.shared.global [%0], [%1], 16;" :: "r"(s), "l"(gsrc));
}
__device__ __forceinline__ void cpa_commit() {
    asm volatile("cp.async.commit_group;" ::: "memory");
}
__device__ __forceinline__ void cpa_wait1() {
    asm volatile("cp.async.wait_group 1;" ::: "memory");
}

__global__ __launch_bounds__(256) void gemm_tf32(
    const float* __restrict__ A_in, int K, int mode,
    const float* __restrict__ W0, const float* __restrict__ W1,
    const float* __restrict__ W2, float* __restrict__ C, int ldc,
    const float* __restrict__ cs, const float* __restrict__ sn)
{
    __shared__ float As[2][BM * ASTR];   // [m][k]
    __shared__ float Bs[2][BK * BSTR];   // [k][n]

    const float* A = (mode == 2) ? g_attn : A_in;

    const int t  = threadIdx.x;
    const int m0 = blockIdx.y * BM;
    const int n0 = blockIdx.x * BN;

    const float* Bp; int ldb; int bc;
    if (mode == 2)                { Bp = W0; ldb = ldc;    bc = n0; }
    else if (n0 < DMODEL)         { Bp = W0; ldb = DMODEL; bc = n0; }
    else if (n0 < DMODEL + KVDIM) { Bp = W1; ldb = KVDIM;  bc = n0 - DMODEL; }
    else                          { Bp = W2; ldb = KVDIM;  bc = n0 - DMODEL - KVDIM; }

    // ---- loader addressing: 512 float4 chunks per tile, 2 per thread ----
    const int ar  = t >> 2;          // A chunk row 0..63 (second chunk: +64)
    const int ac4 = (t & 3) * 4;     // A col (floats)
    const int br  = t >> 5;          // B chunk row 0..7 (second: +8)
    const int bc4 = (t & 31) * 4;    // B col (floats)

    const float* a_src0 = A  + (size_t)(m0 + ar) * K + ac4;
    const float* a_src1 = A  + (size_t)(m0 + ar + 64) * K + ac4;
    const float* b_src0 = Bp + (size_t)br * ldb + bc + bc4;
    const float* b_src1 = Bp + (size_t)(br + 8) * ldb + bc + bc4;

    const int a_d0 = ar * ASTR + ac4;
    const int a_d1 = (ar + 64) * ASTR + ac4;
    const int b_d0 = br * BSTR + bc4;
    const int b_d1 = (br + 8) * BSTR + bc4;

    // ---- mma thread mapping ----
    const int warp = t >> 5, lane = t & 31;
    const int wm = warp >> 1;        // 0..3
    const int wn = warp & 1;         // 0..1
    const int g  = lane >> 2;        // 0..7
    const int q  = lane & 3;         // 0..3

    float acc[2][8][4];
#pragma unroll
    for (int i = 0; i < 2; i++)
#pragma unroll
        for (int j = 0; j < 8; j++)
#pragma unroll
            for (int r = 0; r < 4; r++) acc[i][j][r] = 0.f;

    // prologue: stage 0
    cpa16(&As[0][a_d0], a_src0);
    cpa16(&As[0][a_d1], a_src1);
    cpa16(&Bs[0][b_d0], b_src0);
    cpa16(&Bs[0][b_d1], b_src1);
    cpa_commit();

    const int NIT = K / BK;
    for (int it = 0; it < NIT; it++) {
        if (it + 1 < NIT) {
            const int k0 = (it + 1) * BK;
            const int nb = (it + 1) & 1;
            cpa16(&As[nb][a_d0], a_src0 + k0);
            cpa16(&As[nb][a_d1], a_src1 + k0);
            cpa16(&Bs[nb][b_d0], b_src0 + (size_t)k0 * ldb);
            cpa16(&Bs[nb][b_d1], b_src1 + (size_t)k0 * ldb);
        }
        cpa_commit();        // unconditional: keeps group accounting uniform
        cpa_wait1();
        __syncthreads();

        const float* as = As[it & 1];
        const float* bs = Bs[it & 1];

#pragma unroll
        for (int kc = 0; kc < BK; kc += 8) {
            unsigned a[2][4];
#pragma unroll
            for (int tm = 0; tm < 2; tm++) {
                const float* ap = as + (wm * 32 + tm * 16 + g) * ASTR + kc + q;
                a[tm][0] = f2tf(ap[0]);
                a[tm][1] = f2tf(ap[8 * ASTR]);
                a[tm][2] = f2tf(ap[4]);
                a[tm][3] = f2tf(ap[8 * ASTR + 4]);
            }
#pragma unroll
            for (int tn = 0; tn < 8; tn++) {
                const float* bp = bs + (kc + q) * BSTR + wn * 64 + tn * 8 + g;
                unsigned b0 = f2tf(bp[0]);
                unsigned b1 = f2tf(bp[4 * BSTR]);
                mma_tf32(acc[0][tn], a[0][0], a[0][1], a[0][2], a[0][3], b0, b1);
                mma_tf32(acc[1][tn], a[1][0], a[1][1], a[1][2], a[1][3], b0, b1);
            }
        }
        __syncthreads();
    }

    // ---- epilogue ----
    if (mode == 2) {
#pragma unroll
        for (int tm = 0; tm < 2; tm++) {
            const int row = m0 + wm * 32 + tm * 16 + g;
#pragma unroll
            for (int tn = 0; tn < 8; tn++) {
                const int col = n0 + wn * 64 + tn * 8 + 2 * q;
                *(float2*)(C + (size_t)row * ldc + col) =
                    make_float2(acc[tm][tn][0], acc[tm][tn][1]);
                *(float2*)(C + (size_t)(row + 8) * ldc + col) =
                    make_float2(acc[tm][tn][2], acc[tm][tn][3]);
            }
        }
    } else {
        // scatter into [b][h][s][d] scratch; fuse RoPE for Q/K heads.
        const int b    = m0 >> 11;
        const int sb   = m0 & (S_LEN - 1);
        float* base; bool rope;
        if (n0 < DMODEL) {
            base = g_q + (size_t)(b * NH + (n0 >> 7)) * S_LEN * HD; rope = true;
        } else if (n0 < DMODEL + KVDIM) {
            base = g_k + (size_t)(b * NKV + ((n0 - DMODEL) >> 7)) * S_LEN * HD; rope = true;
        } else {
            base = g_v + (size_t)(b * NKV + ((n0 - DMODEL - KVDIM) >> 7)) * S_LEN * HD; rope = false;
        }
#pragma unroll
        for (int tm = 0; tm < 2; tm++) {
#pragma unroll
            for (int rr = 0; rr < 2; rr++) {
                const int srow = sb + wm * 32 + tm * 16 + g + rr * 8;
#pragma unroll
                for (int tn = 0; tn < 8; tn++) {
                    const int cih = wn * 64 + tn * 8 + 2 * q;   // col within head
                    float re = acc[tm][tn][rr * 2 + 0];
                    float im = acc[tm][tn][rr * 2 + 1];
                    if (rope) {
                        const int j = cih >> 1;
                        const float c = cs[srow * 64 + j];
                        const float s = sn[srow * 64 + j];
                        const float r2 = re * c - im * s;
                        im = re * s + im * c;
                        re = r2;
                    }
                    *(float2*)(base + (size_t)srow * HD + cih) = make_float2(re, im);
                }
            }
        }
    }
}

// ---------------- flash attention: BQ=64, BK=64, full (non-causal) softmax ------
// grid: (S/64, B*NH), 256 threads. smem: Qt[128][68] + KV(max 128*68) + P[64][68]
#define ATTN_SMEM ((128 * 68 + 128 * 68 + 64 * 68) * 4)

__global__ __launch_bounds__(256) void attn_kernel()
{
    extern __shared__ float sm[];
    float* sQ  = sm;                 // Q transposed: sQ[d*68 + r], pre-scaled
    float* sKV = sm + 128 * 68;      // K transposed (d*68+c) then V natural (kk*128+d)
    float* sP  = sm + 2 * 128 * 68;  // probs: sP[r*68 + c]

    const int t  = threadIdx.x;
    const int qt = blockIdx.x;       // q tile 0..31
    const int bh = blockIdx.y;       // 0..63
    const int b  = bh >> 5;
    const int h  = bh & 31;
    const int g  = h >> 2;           // kv head

    const float* qbase = g_q + ((size_t)bh * S_LEN + qt * 64) * HD;
    const float* kbase = g_k + (size_t)(b * NKV + g) * S_LEN * HD;
    const float* vbase = g_v + (size_t)(b * NKV + g) * S_LEN * HD;

    const float scale = 0.08838834764831845f;  // 1/sqrt(128)

    // load Q tile transposed, folded scale
#pragma unroll
    for (int i = 0; i < 32; i++) {
        int idx = t + i * 256;               // 0..8191
        sQ[(idx & 127) * 68 + (idx >> 7)] = qbase[idx] * scale;
    }

    const int ty = t >> 4, tx = t & 15;
    const int r0 = ty * 4, c0 = tx * 4, oc0 = tx * 8;

    float m_i[4], l_i[4], o[4][8];
#pragma unroll
    for (int i = 0; i < 4; i++) {
        m_i[i] = -1e30f; l_i[i] = 0.f;
#pragma unroll
        for (int j = 0; j < 8; j++) o[i][j] = 0.f;
    }

    for (int kt = 0; kt < S_LEN / 64; kt++) {
        __syncthreads();  // prev PV done (and Q ready on iter 0)

        // load K tile transposed
        const float* kp = kbase + (size_t)kt * 64 * HD;
#pragma unroll
        for (int i = 0; i < 32; i++) {
            int idx = t + i * 256;
            sKV[(idx & 127) * 68 + (idx >> 7)] = kp[idx];
        }
        __syncthreads();

        // S = Q K^T (4x4 per thread)
        float s[4][4];
#pragma unroll
        for (int i = 0; i < 4; i++)
#pragma unroll
            for (int j = 0; j < 4; j++) s[i][j] = 0.f;

#pragma unroll 8
        for (int d = 0; d < 128; d++) {
            float4 a  = *(const float4*)&sQ [d * 68 + r0];
            float4 bb = *(const float4*)&sKV[d * 68 + c0];
            float av[4] = {a.x, a.y, a.z, a.w};
            float bv[4] = {bb.x, bb.y, bb.z, bb.w};
#pragma unroll
            for (int i = 0; i < 4; i++)
#pragma unroll
                for (int j = 0; j < 4; j++)
                    s[i][j] = fmaf(av[i], bv[j], s[i][j]);
        }

        // online softmax (rows shared by the 16 tx lanes -> shfl reduce)
        float alpha[4];
#pragma unroll
        for (int i = 0; i < 4; i++) {
            float mx = fmaxf(fmaxf(s[i][0], s[i][1]), fmaxf(s[i][2], s[i][3]));
#pragma unroll
            for (int off = 8; off > 0; off >>= 1)
                mx = fmaxf(mx, __shfl_xor_sync(0xffffffffu, mx, off));
            float mnew = fmaxf(m_i[i], mx);
            float al   = __expf(m_i[i] - mnew);
            m_i[i] = mnew;
            float sum = 0.f;
#pragma unroll
            for (int j = 0; j < 4; j++) { s[i][j] = __expf(s[i][j] - mnew); sum += s[i][j]; }
#pragma unroll
            for (int off = 8; off > 0; off >>= 1)
                sum += __shfl_xor_sync(0xffffffffu, sum, off);
            l_i[i] = l_i[i] * al + sum;
            alpha[i] = al;
        }

        // stash probs
#pragma unroll
        for (int i = 0; i < 4; i++)
#pragma unroll
            for (int j = 0; j < 4; j++)
                sP[(r0 + i) * 68 + c0 + j] = s[i][j];
        __syncthreads();  // done reading K-tile + all P written

        // load V tile (natural layout) into same buffer
        const float* vp = vbase + (size_t)kt * 64 * HD;
#pragma unroll
        for (int i = 0; i < 32; i++) {
            int idx = t + i * 256;
            sKV[idx] = vp[idx];
        }
        __syncthreads();

        // rescale + O += P V
#pragma unroll
        for (int i = 0; i < 4; i++) {
            float al = alpha[i];
#pragma unroll
            for (int j = 0; j < 8; j++) o[i][j] *= al;
        }
#pragma unroll 4
        for (int kk = 0; kk < 64; kk++) {
            float4 v0 = *(const float4*)&sKV[kk * 128 + oc0];
            float4 v1 = *(const float4*)&sKV[kk * 128 + oc0 + 4];
            float vv[8] = {v0.x, v0.y, v0.z, v0.w, v1.x, v1.y, v1.z, v1.w};
#pragma unroll
            for (int i = 0; i < 4; i++) {
                float p = sP[(r0 + i) * 68 + kk];
#pragma unroll
                for (int j = 0; j < 8; j++)
                    o[i][j] = fmaf(p, vv[j], o[i][j]);
            }
        }
    }

    // normalize + write to g_attn [b*s][h*128+d]
#pragma unroll
    for (int i = 0; i < 4; i++) {
        float inv = 1.f / l_i[i];
        int srow  = qt * 64 + r0 + i;
        float* op = g_attn + ((size_t)(b * S_LEN + srow)) * DMODEL + h * HD + oc0;
        *(float4*)op       = make_float4(o[i][0] * inv, o[i][1] * inv, o[i][2] * inv, o[i][3] * inv);
        *(float4*)(op + 4) = make_float4(o[i][4] * inv, o[i][5] * inv, o[i][6] * inv, o[i][7] * inv);
    }
}

// ---------------- launch ---------------------------------------------------------
extern "C" void kernel_launch(void* const* d_in, const int* in_sizes, int n_in,
                              void* d_out, int out_size)
{
    const float* x  = (const float*)d_in[0];
    const float* cs = (const float*)d_in[1];
    const float* sn = (const float*)d_in[2];
    const float* wq = (const float*)d_in[3];
    const float* wk = (const float*)d_in[4];
    const float* wv = (const float*)d_in[5];
    const float* wo = (const float*)d_in[6];
    // d_in[7] = start_pos (always 0 for this problem)
    float* out = (float*)d_out;

    cudaFuncSetAttribute(attn_kernel, cudaFuncAttributeMaxDynamicSharedMemorySize, ATTN_SMEM);

    // 1) fused QKV projection (tf32 tensor cores) + RoPE-fused scatter
    gemm_tf32<<<dim3((DMODEL + 2 * KVDIM) / BN, (B_SZ * S_LEN) / BM), 256>>>(
        x, DMODEL, 1, wq, wk, wv, nullptr, 0, cs, sn);

    // 2) attention
    attn_kernel<<<dim3(S_LEN / 64, B_SZ * NH), 256, ATTN_SMEM>>>();

    // 3) output projection (tf32 tensor cores)
    gemm_tf32<<<dim3(DMODEL / BN, (B_SZ * S_LEN) / BM), 256>>>(
        nullptr, DMODEL, 2, wo, nullptr, nullptr, out, DMODEL, nullptr, nullptr);
}

// round 6
// speedup vs baseline: 5.6250x; 1.8944x over previous
#include <cuda_runtime.h>
#include <math.h>

#define S_LEN  2048
#define B_SZ   2
#define DMODEL 4096
#define KVDIM  1024
#define HD     128
#define NH     32
#define NKV    8

// ---------------- scratch (static device globals; no allocation) ----------------
// tf32-bit operand copies (converted once per launch)
__device__ unsigned g_x [(size_t)B_SZ * S_LEN * DMODEL];
__device__ unsigned g_wq[(size_t)DMODEL * DMODEL];
__device__ unsigned g_wk[(size_t)DMODEL * KVDIM];
__device__ unsigned g_wv[(size_t)DMODEL * KVDIM];
__device__ unsigned g_wo[(size_t)DMODEL * DMODEL];
// intermediates (tf32 bits)
__device__ unsigned g_q[(size_t)B_SZ * NH  * S_LEN * HD];   // [b][h][s][d]
__device__ unsigned g_k[(size_t)B_SZ * NKV * S_LEN * HD];   // [b][g][s][d]
__device__ unsigned g_v[(size_t)B_SZ * NKV * S_LEN * HD];   // [b][g][s][d]
__device__ unsigned g_attn[(size_t)B_SZ * S_LEN * DMODEL];  // [b*s][h*128+d]

// ---------------- helpers --------------------------------------------------------
__device__ __forceinline__ unsigned f2tf(float f) {
    unsigned u;
    asm("cvt.rna.tf32.f32 %0, %1;" : "=r"(u) : "f"(f));
    return u;
}

__device__ __forceinline__ void mma_tf32(float c[4],
    unsigned a0, unsigned a1, unsigned a2, unsigned a3,
    unsigned b0, unsigned b1)
{
    asm volatile(
        "mma.sync.aligned.m16n8k8.row.col.f32.tf32.tf32.f32 "
        "{%0,%1,%2,%3}, {%4,%5,%6,%7}, {%8,%9}, {%0,%1,%2,%3};"
        : "+f"(c[0]), "+f"(c[1]), "+f"(c[2]), "+f"(c[3])
        : "r"(a0), "r"(a1), "r"(a2), "r"(a3), "r"(b0), "r"(b1));
}

__device__ __forceinline__ void cpa16(void* smem_dst, const void* gsrc) {
    unsigned s = (unsigned)__cvta_generic_to_shared(smem_dst);
    asm volatile("cp.async.cg.shared.global [%0], [%1], 16;" :: "r"(s), "l"(gsrc));
}
__device__ __forceinline__ void cpa_commit() {
    asm volatile("cp.async.commit_group;" ::: "memory");
}
__device__ __forceinline__ void cpa_wait1() {
    asm volatile("cp.async.wait_group 1;" ::: "memory");
}
__device__ __forceinline__ void cpa_wait0() {
    asm volatile("cp.async.wait_group 0;" ::: "memory");
}

// ---------------- tf32 pre-conversion kernel ------------------------------------
__global__ __launch_bounds__(256) void cvt_tf32(const float4* __restrict__ src,
                                                int which, int n4)
{
    int i = blockIdx.x * blockDim.x + threadIdx.x;
    if (i >= n4) return;
    uint4* dst = (which == 0) ? (uint4*)g_x
               : (which == 1) ? (uint4*)g_wq
               : (which == 2) ? (uint4*)g_wk
               : (which == 3) ? (uint4*)g_wv
                              : (uint4*)g_wo;
    float4 f = src[i];
    uint4 u;
    u.x = f2tf(f.x); u.y = f2tf(f.y); u.z = f2tf(f.z); u.w = f2tf(f.w);
    dst[i] = u;
}

// ================= TF32 tensor-core GEMM (pre-converted operands) ================
// 128x128 CTA tile, BK=16, 256 threads = 8 warps as 4(m) x 2(n), warp tile 32x64.
// mode 1: A = g_x, fused QKV (g_wq/g_wk/g_wv), epilogue RoPE + scatter (tf32 bits)
// mode 2: A = g_attn, C = A @ g_wo, fp32 row-major store.
#define BM 128
#define BN 128
#define BK 16
#define ASTR 20
#define BSTR 136

__global__ __launch_bounds__(256) void gemm_tf32(
    int K, int mode, float* __restrict__ C, int ldc,
    const float* __restrict__ cs, const float* __restrict__ sn)
{
    __shared__ unsigned As[2][BM * ASTR];   // [m][k]
    __shared__ unsigned Bs[2][BK * BSTR];   // [k][n]

    const unsigned* A = (mode == 2) ? g_attn : g_x;

    const int t  = threadIdx.x;
    const int m0 = blockIdx.y * BM;
    const int n0 = blockIdx.x * BN;

    const unsigned* Bp; int ldb; int bc;
    if (mode == 2)                { Bp = g_wo; ldb = DMODEL; bc = n0; }
    else if (n0 < DMODEL)         { Bp = g_wq; ldb = DMODEL; bc = n0; }
    else if (n0 < DMODEL + KVDIM) { Bp = g_wk; ldb = KVDIM;  bc = n0 - DMODEL; }
    else                          { Bp = g_wv; ldb = KVDIM;  bc = n0 - DMODEL - KVDIM; }

    const int ar  = t >> 2;
    const int ac4 = (t & 3) * 4;
    const int br  = t >> 5;
    const int bc4 = (t & 31) * 4;

    const unsigned* a_src0 = A  + (size_t)(m0 + ar) * K + ac4;
    const unsigned* a_src1 = A  + (size_t)(m0 + ar + 64) * K + ac4;
    const unsigned* b_src0 = Bp + (size_t)br * ldb + bc + bc4;
    const unsigned* b_src1 = Bp + (size_t)(br + 8) * ldb + bc + bc4;

    const int a_d0 = ar * ASTR + ac4;
    const int a_d1 = (ar + 64) * ASTR + ac4;
    const int b_d0 = br * BSTR + bc4;
    const int b_d1 = (br + 8) * BSTR + bc4;

    const int warp = t >> 5, lane = t & 31;
    const int wm = warp >> 1;
    const int wn = warp & 1;
    const int g  = lane >> 2;
    const int q  = lane & 3;

    float acc[2][8][4];
#pragma unroll
    for (int i = 0; i < 2; i++)
#pragma unroll
        for (int j = 0; j < 8; j++)
#pragma unroll
            for (int r = 0; r < 4; r++) acc[i][j][r] = 0.f;

    cpa16(&As[0][a_d0], a_src0);
    cpa16(&As[0][a_d1], a_src1);
    cpa16(&Bs[0][b_d0], b_src0);
    cpa16(&Bs[0][b_d1], b_src1);
    cpa_commit();

    const int NIT = K / BK;
    for (int it = 0; it < NIT; it++) {
        if (it + 1 < NIT) {
            const int k0 = (it + 1) * BK;
            const int nb = (it + 1) & 1;
            cpa16(&As[nb][a_d0], a_src0 + k0);
            cpa16(&As[nb][a_d1], a_src1 + k0);
            cpa16(&Bs[nb][b_d0], b_src0 + (size_t)k0 * ldb);
            cpa16(&Bs[nb][b_d1], b_src1 + (size_t)k0 * ldb);
        }
        cpa_commit();
        cpa_wait1();
        __syncthreads();

        const unsigned* as = As[it & 1];
        const unsigned* bs = Bs[it & 1];

#pragma unroll
        for (int kc = 0; kc < BK; kc += 8) {
            unsigned a[2][4];
#pragma unroll
            for (int tm = 0; tm < 2; tm++) {
                const unsigned* ap = as + (wm * 32 + tm * 16 + g) * ASTR + kc + q;
                a[tm][0] = ap[0];
                a[tm][1] = ap[8 * ASTR];
                a[tm][2] = ap[4];
                a[tm][3] = ap[8 * ASTR + 4];
            }
#pragma unroll
            for (int tn = 0; tn < 8; tn++) {
                const unsigned* bp = bs + (kc + q) * BSTR + wn * 64 + tn * 8 + g;
                unsigned b0 = bp[0];
                unsigned b1 = bp[4 * BSTR];
                mma_tf32(acc[0][tn], a[0][0], a[0][1], a[0][2], a[0][3], b0, b1);
                mma_tf32(acc[1][tn], a[1][0], a[1][1], a[1][2], a[1][3], b0, b1);
            }
        }
        __syncthreads();
    }

    if (mode == 2) {
#pragma unroll
        for (int tm = 0; tm < 2; tm++) {
            const int row = m0 + wm * 32 + tm * 16 + g;
#pragma unroll
            for (int tn = 0; tn < 8; tn++) {
                const int col = n0 + wn * 64 + tn * 8 + 2 * q;
                *(float2*)(C + (size_t)row * ldc + col) =
                    make_float2(acc[tm][tn][0], acc[tm][tn][1]);
                *(float2*)(C + (size_t)(row + 8) * ldc + col) =
                    make_float2(acc[tm][tn][2], acc[tm][tn][3]);
            }
        }
    } else {
        const int b    = m0 >> 11;
        const int sb   = m0 & (S_LEN - 1);
        unsigned* base; bool rope;
        if (n0 < DMODEL) {
            base = g_q + (size_t)(b * NH + (n0 >> 7)) * S_LEN * HD; rope = true;
        } else if (n0 < DMODEL + KVDIM) {
            base = g_k + (size_t)(b * NKV + ((n0 - DMODEL) >> 7)) * S_LEN * HD; rope = true;
        } else {
            base = g_v + (size_t)(b * NKV + ((n0 - DMODEL - KVDIM) >> 7)) * S_LEN * HD; rope = false;
        }
#pragma unroll
        for (int tm = 0; tm < 2; tm++) {
#pragma unroll
            for (int rr = 0; rr < 2; rr++) {
                const int srow = sb + wm * 32 + tm * 16 + g + rr * 8;
#pragma unroll
                for (int tn = 0; tn < 8; tn++) {
                    const int cih = wn * 64 + tn * 8 + 2 * q;
                    float re = acc[tm][tn][rr * 2 + 0];
                    float im = acc[tm][tn][rr * 2 + 1];
                    if (rope) {
                        const int j = cih >> 1;
                        const float c = cs[srow * 64 + j];
                        const float s = sn[srow * 64 + j];
                        const float r2 = re * c - im * s;
                        im = re * s + im * c;
                        re = r2;
                    }
                    uint2 u; u.x = f2tf(re); u.y = f2tf(im);
                    *(uint2*)(base + (size_t)srow * HD + cih) = u;
                }
            }
        }
    }
}

// ================= flash attention on tensor cores (tf32 mma) =====================
// BQ=128, BKV=64. 256 threads = 8 warps, each owns 16 q-rows (full 64 kv cols).
// smem: Q[128][132] + 2 x { K[64][132] (reused as P[128][68]) , V[64][136] }.
#define AQ_STR 132
#define AK_STR 132
#define AV_STR 136
#define AP_STR 68
#define KV_REG 8704                       // uints: K region (== P region exactly)
#define BUF_UINTS (KV_REG * 2)            // K + V
#define Q_UINTS (128 * AQ_STR)
#define ATTN_SMEM ((Q_UINTS + 2 * BUF_UINTS) * 4)

__device__ __forceinline__ void attn_issue_kv(
    unsigned* sm, int t, int kt, int bi,
    const unsigned* kg, const unsigned* vg)
{
    unsigned* kb = sm + Q_UINTS + bi * BUF_UINTS;
    unsigned* vb = kb + KV_REG;
    const unsigned* ks = kg + (size_t)kt * 64 * HD;
    const unsigned* vs = vg + (size_t)kt * 64 * HD;
#pragma unroll
    for (int i = 0; i < 8; i++) {
        int c  = t + i * 256;
        int r  = c >> 5;
        int c4 = (c & 31) * 4;
        cpa16(&kb[r * AK_STR + c4], ks + (size_t)r * HD + c4);
        cpa16(&vb[r * AV_STR + c4], vs + (size_t)r * HD + c4);
    }
}

__global__ __launch_bounds__(256, 1) void attn_kernel()
{
    extern __shared__ unsigned sm[];
    unsigned* sQ = sm;

    const int t    = threadIdx.x;
    const int warp = t >> 5, lane = t & 31;
    const int g    = lane >> 2, q = lane & 3;
    const int qt   = blockIdx.x;          // 0..15
    const int bh   = blockIdx.y;          // 0..63
    const int b    = bh >> 5;
    const int h    = bh & 31;
    const int kvh  = h >> 2;

    const unsigned* qg = g_q + ((size_t)bh * S_LEN + qt * 128) * HD;
    const unsigned* kg = g_k + (size_t)(b * NKV + kvh) * S_LEN * HD;
    const unsigned* vg = g_v + (size_t)(b * NKV + kvh) * S_LEN * HD;

    // prologue: Q + tile0 (group 0), tile1 (group 1)
#pragma unroll
    for (int i = 0; i < 16; i++) {
        int c  = t + i * 256;
        int r  = c >> 5;
        int c4 = (c & 31) * 4;
        cpa16(&sQ[r * AQ_STR + c4], qg + (size_t)r * HD + c4);
    }
    attn_issue_kv(sm, t, 0, 0, kg, vg);
    cpa_commit();
    attn_issue_kv(sm, t, 1, 1, kg, vg);
    cpa_commit();

    const float scale = 0.08838834764831845f;   // 1/sqrt(128)

    float accO[16][4];
#pragma unroll
    for (int nf = 0; nf < 16; nf++)
#pragma unroll
        for (int r = 0; r < 4; r++) accO[nf][r] = 0.f;
    float m0v = -1e30f, m1v = -1e30f, l0 = 0.f, l1 = 0.f;

    const int aoffQ = (warp * 16 + g) * AQ_STR + q;

    for (int kt = 0; kt < S_LEN / 64; kt++) {
        unsigned* kb = sm + Q_UINTS + (kt & 1) * BUF_UINTS;
        unsigned* vb = kb + KV_REG;

        cpa_wait1();           // group kt complete (Q included in group 0)
        __syncthreads();

        // ---- S = Q K^T ----
        float accS[8][4];
#pragma unroll
        for (int nf = 0; nf < 8; nf++)
#pragma unroll
            for (int r = 0; r < 4; r++) accS[nf][r] = 0.f;

#pragma unroll
        for (int kc = 0; kc < 128; kc += 8) {
            unsigned a0 = sQ[aoffQ + kc];
            unsigned a1 = sQ[aoffQ + kc + 8 * AQ_STR];
            unsigned a2 = sQ[aoffQ + kc + 4];
            unsigned a3 = sQ[aoffQ + kc + 8 * AQ_STR + 4];
#pragma unroll
            for (int nf = 0; nf < 8; nf++) {
                const int bo = (nf * 8 + g) * AK_STR + kc + q;
                mma_tf32(accS[nf], a0, a1, a2, a3, kb[bo], kb[bo + 4]);
            }
        }

        // ---- online softmax (rows g and g+8 of this warp's 16) ----
        float al0, al1;
        {
            float mx = -1e30f;
#pragma unroll
            for (int nf = 0; nf < 8; nf++)
                mx = fmaxf(mx, fmaxf(accS[nf][0], accS[nf][1]));
            mx *= scale;
            mx = fmaxf(mx, __shfl_xor_sync(0xffffffffu, mx, 1));
            mx = fmaxf(mx, __shfl_xor_sync(0xffffffffu, mx, 2));
            float mn = fmaxf(m0v, mx);
            al0 = __expf(m0v - mn); m0v = mn;
            float s = 0.f;
#pragma unroll
            for (int nf = 0; nf < 8; nf++) {
                float p0 = __expf(accS[nf][0] * scale - mn);
                float p1 = __expf(accS[nf][1] * scale - mn);
                accS[nf][0] = p0; accS[nf][1] = p1; s += p0 + p1;
            }
            s += __shfl_xor_sync(0xffffffffu, s, 1);
            s += __shfl_xor_sync(0xffffffffu, s, 2);
            l0 = l0 * al0 + s;
        }
        {
            float mx = -1e30f;
#pragma unroll
            for (int nf = 0; nf < 8; nf++)
                mx = fmaxf(mx, fmaxf(accS[nf][2], accS[nf][3]));
            mx *= scale;
            mx = fmaxf(mx, __shfl_xor_sync(0xffffffffu, mx, 1));
            mx = fmaxf(mx, __shfl_xor_sync(0xffffffffu, mx, 2));
            float mn = fmaxf(m1v, mx);
            al1 = __expf(m1v - mn); m1v = mn;
            float s = 0.f;
#pragma unroll
            for (int nf = 0; nf < 8; nf++) {
                float p0 = __expf(accS[nf][2] * scale - mn);
                float p1 = __expf(accS[nf][3] * scale - mn);
                accS[nf][2] = p0; accS[nf][3] = p1; s += p0 + p1;
            }
            s += __shfl_xor_sync(0xffffffffu, s, 1);
            s += __shfl_xor_sync(0xffffffffu, s, 2);
            l1 = l1 * al1 + s;
        }

        __syncthreads();   // all warps done reading K tile

        // ---- store P (tf32 bits) into the consumed K region; rescale O ----
        unsigned* sP = kb;
        const int pr = (warp * 16 + g) * AP_STR;
#pragma unroll
        for (int nf = 0; nf < 8; nf++) {
            uint2 u0; u0.x = f2tf(accS[nf][0]); u0.y = f2tf(accS[nf][1]);
            *(uint2*)&sP[pr + nf * 8 + 2 * q] = u0;
            uint2 u1; u1.x = f2tf(accS[nf][2]); u1.y = f2tf(accS[nf][3]);
            *(uint2*)&sP[pr + 8 * AP_STR + nf * 8 + 2 * q] = u1;
        }
#pragma unroll
        for (int nf = 0; nf < 16; nf++) {
            accO[nf][0] *= al0; accO[nf][1] *= al0;
            accO[nf][2] *= al1; accO[nf][3] *= al1;
        }
        __syncthreads();   // P visible

        // ---- O += P V ----
        const int po = (warp * 16 + g) * AP_STR + q;
#pragma unroll
        for (int kc = 0; kc < 64; kc += 8) {
            unsigned a0 = sP[po + kc];
            unsigned a1 = sP[po + kc + 8 * AP_STR];
            unsigned a2 = sP[po + kc + 4];
            unsigned a3 = sP[po + kc + 8 * AP_STR + 4];
#pragma unroll
            for (int nf = 0; nf < 16; nf++) {
                const int bo = (kc + q) * AV_STR + nf * 8 + g;
                mma_tf32(accO[nf], a0, a1, a2, a3, vb[bo], vb[bo + 4 * AV_STR]);
            }
        }
        __syncthreads();   // buffer fully consumed

        if (kt + 2 < S_LEN / 64)
            attn_issue_kv(sm, t, kt + 2, kt & 1, kg, vg);
        cpa_commit();
    }
    cpa_wait0();

    // ---- normalize + write tf32 bits to g_attn ----
    const float inv0 = 1.f / l0, inv1 = 1.f / l1;
    const int r0 = qt * 128 + warp * 16 + g;
    unsigned* ob0 = g_attn + ((size_t)b * S_LEN + r0) * DMODEL + h * HD;
    unsigned* ob1 = ob0 + (size_t)8 * DMODEL;
#pragma unroll
    for (int nf = 0; nf < 16; nf++) {
        const int col = nf * 8 + 2 * q;
        uint2 u0; u0.x = f2tf(accO[nf][0] * inv0); u0.y = f2tf(accO[nf][1] * inv0);
        *(uint2*)&ob0[col] = u0;
        uint2 u1; u1.x = f2tf(accO[nf][2] * inv1); u1.y = f2tf(accO[nf][3] * inv1);
        *(uint2*)&ob1[col] = u1;
    }
}

// ---------------- launch ---------------------------------------------------------
extern "C" void kernel_launch(void* const* d_in, const int* in_sizes, int n_in,
                              void* d_out, int out_size)
{
    const float* x  = (const float*)d_in[0];
    const float* cs = (const float*)d_in[1];
    const float* sn = (const float*)d_in[2];
    const float* wq = (const float*)d_in[3];
    const float* wk = (const float*)d_in[4];
    const float* wv = (const float*)d_in[5];
    const float* wo = (const float*)d_in[6];
    float* out = (float*)d_out;

    cudaFuncSetAttribute(attn_kernel, cudaFuncAttributeMaxDynamicSharedMemorySize, ATTN_SMEM);

    // 0) pre-convert operands to tf32 bits (rna)
    const int nx  = B_SZ * S_LEN * DMODEL / 4;   // 4,194,304
    const int nqo = DMODEL * DMODEL / 4;          // 4,194,304
    const int nkv = DMODEL * KVDIM / 4;           // 1,048,576
    cvt_tf32<<<nx  / 256, 256>>>((const float4*)x,  0, nx);
    cvt_tf32<<<nqo / 256, 256>>>((const float4*)wq, 1, nqo);
    cvt_tf32<<<nkv / 256, 256>>>((const float4*)wk, 2, nkv);
    cvt_tf32<<<nkv / 256, 256>>>((const float4*)wv, 3, nkv);
    cvt_tf32<<<nqo / 256, 256>>>((const float4*)wo, 4, nqo);

    // 1) fused QKV projection + RoPE-fused tf32 scatter
    gemm_tf32<<<dim3((DMODEL + 2 * KVDIM) / BN, (B_SZ * S_LEN) / BM), 256>>>(
        DMODEL, 1, nullptr, 0, cs, sn);

    // 2) attention (tensor cores)
    attn_kernel<<<dim3(S_LEN / 128, B_SZ * NH), 256, ATTN_SMEM>>>();

    // 3) output projection
    gemm_tf32<<<dim3(DMODEL / BN, (B_SZ * S_LEN) / BM), 256>>>(
        DMODEL, 2, out, DMODEL, nullptr, nullptr);
}

// round 8
// speedup vs baseline: 7.1831x; 1.2770x over previous
#include <cuda_runtime.h>
#include <math.h>
#include <stdint.h>

#define S_LEN  2048
#define B_SZ   2
#define DMODEL 4096
#define KVDIM  1024
#define HD     128
#define NH     32
#define NKV    8

// ---------------- scratch (static device globals; no allocation) ----------------
// fragment-packed tf32 operands (see pack layout below)
__device__ unsigned g_xp [(size_t)B_SZ * S_LEN * DMODEL];   // x packed-A
__device__ unsigned g_wqp[(size_t)DMODEL * DMODEL];          // wq packed-B
__device__ unsigned g_wkp[(size_t)DMODEL * KVDIM];           // wk packed-B
__device__ unsigned g_wvp[(size_t)DMODEL * KVDIM];           // wv packed-B
__device__ unsigned g_wop[(size_t)DMODEL * DMODEL];          // wo packed-B
// intermediates (tf32 bits)
__device__ unsigned g_q[(size_t)B_SZ * NH  * S_LEN * HD];   // [b][h][s][d] row-major
__device__ unsigned g_k[(size_t)B_SZ * NKV * S_LEN * HD];
__device__ unsigned g_v[(size_t)B_SZ * NKV * S_LEN * HD];
__device__ unsigned g_attn[(size_t)B_SZ * S_LEN * DMODEL];  // packed-A layout

// Packed-A layout (M x K): stages of (128 rows x 16 k) = 2048 uints, indexed
//   [kblk = k/16][mb = m/128] -> stage; within: [mt(8)][kt(2)][lane(32)][slot(4)]
//   lane = (row&7)*4 + (k&3); slots = (g,q),(g+8,q),(g,q+4),(g+8,q+4)
// Packed-B layout (N x K, weights): stages of (128 n x 16 k) = 2048 uints, indexed
//   [kblk][nb = n/128]; within: [kt(2)][n64(2)][j(4)][lane(32)][slot(4)]
//   lane = (n&7)*4 + (k&3); slots = (n=j*16+g,k=q),(same n,q+4),(n+8,q),(n+8,q+4)

// ---------------- helpers --------------------------------------------------------
__device__ __forceinline__ unsigned f2tf(float f) {
    unsigned u;
    asm("cvt.rna.tf32.f32 %0, %1;" : "=r"(u) : "f"(f));
    return u;
}

__device__ __forceinline__ void mma_tf32(float c[4],
    unsigned a0, unsigned a1, unsigned a2, unsigned a3,
    unsigned b0, unsigned b1)
{
    asm volatile(
        "mma.sync.aligned.m16n8k8.row.col.f32.tf32.tf32.f32 "
        "{%0,%1,%2,%3}, {%4,%5,%6,%7}, {%8,%9}, {%0,%1,%2,%3};"
        : "+f"(c[0]), "+f"(c[1]), "+f"(c[2]), "+f"(c[3])
        : "r"(a0), "r"(a1), "r"(a2), "r"(a3), "r"(b0), "r"(b1));
}

__device__ __forceinline__ void cpa16(void* smem_dst, const void* gsrc) {
    unsigned s = (unsigned)__cvta_generic_to_shared(smem_dst);
    asm volatile("cp.async.cg.shared.global [%0], [%1], 16;" :: "r"(s), "l"(gsrc));
}
__device__ __forceinline__ void cpa_commit() {
    asm volatile("cp.async.commit_group;" ::: "memory");
}
__device__ __forceinline__ void cpa_wait1() {
    asm volatile("cp.async.wait_group 1;" ::: "memory");
}
__device__ __forceinline__ void cpa_wait3() {
    asm volatile("cp.async.wait_group 3;" ::: "memory");
}
__device__ __forceinline__ void cpa_wait0() {
    asm volatile("cp.async.wait_group 0;" ::: "memory");
}

// packed-A address (in uints) for element (row r, col c) of an M=4096 matrix
__device__ __forceinline__ size_t packA_addr(int r, int c) {
    const int kblk = c >> 4, mb = r >> 7;
    const int mt = (r >> 4) & 7, kt = (c >> 3) & 1;
    const int gg = r & 15, qq = c & 7;
    const int l = (gg & 7) * 4 + (qq & 3);
    const int slot = (gg >> 3) + ((qq >> 2) << 1);
    return ((size_t)(kblk * 32 + mb) * 2048) + (size_t)((mt * 2 + kt) * 128 + l * 4 + slot);
}

// ---------------- pre-pass: pack x and weights into fragment layouts -------------
__global__ __launch_bounds__(256) void pack_x(const float* __restrict__ x)
{
    const int kblk = blockIdx.x;      // 0..K/16-1
    const int mb   = blockIdx.y;      // 0..31
    uint4* dst = (uint4*)g_xp + ((size_t)kblk * 32 + mb) * 512;
    const int t = threadIdx.x;
#pragma unroll
    for (int i = 0; i < 2; i++) {
        const int id = t + i * 256;            // 0..511
        const int mt = id >> 6;
        const int kt = (id >> 5) & 1;
        const int lane = id & 31;
        const int g = lane >> 2, q = lane & 3;
        const int r = mb * 128 + mt * 16 + g;
        const int c = kblk * 16 + kt * 8 + q;
        uint4 u;
        u.x = f2tf(x[(size_t)r * DMODEL + c]);
        u.y = f2tf(x[(size_t)(r + 8) * DMODEL + c]);
        u.z = f2tf(x[(size_t)r * DMODEL + c + 4]);
        u.w = f2tf(x[(size_t)(r + 8) * DMODEL + c + 4]);
        dst[id] = u;
    }
}

// src [K][N] fp32 row-major -> packed-B.  grid (N/128, K/16), 256 threads.
__global__ __launch_bounds__(256) void pack_w(const float* __restrict__ src,
                                              int which, int N)
{
    unsigned* dsel = (which == 1) ? g_wqp
                   : (which == 2) ? g_wkp
                   : (which == 3) ? g_wvp
                                  : g_wop;
    const int nb = blockIdx.x, kblk = blockIdx.y;
    uint4* dst = (uint4*)dsel + ((size_t)kblk * (N / 128) + nb) * 512;
    const int t = threadIdx.x;
#pragma unroll
    for (int i = 0; i < 2; i++) {
        const int id = t + i * 256;            // 0..511
        const int kt  = id >> 8;
        const int n64 = (id >> 7) & 1;
        const int j   = (id >> 5) & 3;
        const int lane = id & 31;
        const int g = lane >> 2, q = lane & 3;
        const int k = kblk * 16 + kt * 8 + q;
        const int n = nb * 128 + n64 * 64 + j * 16 + g;
        uint4 u;
        u.x = f2tf(src[(size_t)k * N + n]);
        u.y = f2tf(src[(size_t)(k + 4) * N + n]);
        u.z = f2tf(src[(size_t)k * N + n + 8]);
        u.w = f2tf(src[(size_t)(k + 4) * N + n + 8]);
        dst[id] = u;
    }
}

// ================= legacy-mma TF32 GEMM on fragment-packed operands ==============
// 128x128 CTA tile, BK=16, 256 threads = 8 warps (4m x 2n), warp tile 32x64.
// 4-stage cp.async pipeline, stage = 8KB A + 8KB B, all copies/LDS.128 linear.
// mode 1: A=g_xp, B = {g_wqp|g_wkp|g_wvp}; epilogue RoPE + row-major tf32 scatter.
// mode 2: A=g_attn (packed), B=g_wop; fp32 row-major store to C.
#define GSTG 4
#define GEMM_SMEM (GSTG * 16384)

__global__ __launch_bounds__(256, 2) void gemm_pk(
    int mode, float* __restrict__ C,
    const float* __restrict__ cs, const float* __restrict__ sn)
{
    extern __shared__ uint4 sm4[];

    const int t    = threadIdx.x;
    const int warp = t >> 5, lane = t & 31;
    const int wm   = warp >> 1, wn = warp & 1;
    const int g    = lane >> 2, q = lane & 3;
    const int m0   = blockIdx.y * 128;
    const int n0   = blockIdx.x * 128;
    const int mb   = blockIdx.y;

    const uint4* Asrc = ((mode == 2) ? (const uint4*)g_attn : (const uint4*)g_xp)
                        + (size_t)mb * 512;
    const size_t astride = 32 * 512;          // uint4 per kblk step

    const uint4* Bsrc; size_t bstride;
    if (mode == 2) {
        Bsrc = (const uint4*)g_wop + (size_t)(n0 >> 7) * 512;               bstride = 32 * 512;
    } else if (n0 < DMODEL) {
        Bsrc = (const uint4*)g_wqp + (size_t)(n0 >> 7) * 512;               bstride = 32 * 512;
    } else if (n0 < DMODEL + KVDIM) {
        Bsrc = (const uint4*)g_wkp + (size_t)((n0 - DMODEL) >> 7) * 512;    bstride = 8 * 512;
    } else {
        Bsrc = (const uint4*)g_wvp + (size_t)((n0 - DMODEL - KVDIM) >> 7) * 512; bstride = 8 * 512;
    }

    float acc[2][8][4];
#pragma unroll
    for (int i = 0; i < 2; i++)
#pragma unroll
        for (int j = 0; j < 8; j++)
#pragma unroll
            for (int r = 0; r < 4; r++) acc[i][j][r] = 0.f;

    // prologue: 4 stages
#pragma unroll
    for (int st = 0; st < GSTG; st++) {
        const uint4* Ak = Asrc + (size_t)st * astride;
        const uint4* Bk = Bsrc + (size_t)st * bstride;
        uint4* d = sm4 + st * 1024;
        cpa16(&d[t],       Ak + t);
        cpa16(&d[t + 256], Ak + t + 256);
        cpa16(&d[t + 512], Bk + t);
        cpa16(&d[t + 768], Bk + t + 256);
        cpa_commit();
    }

    const int NIT = DMODEL / 16;   // 256
    for (int it = 0; it < NIT; it++) {
        const int s = it & 3;
        cpa_wait3();
        __syncthreads();

        const uint4* ap = sm4 + s * 1024;
        const uint4* bp = ap + 512;

#pragma unroll
        for (int kc = 0; kc < 2; kc++) {
            const uint4 a0 = ap[((wm * 2 + 0) * 2 + kc) * 32 + lane];
            const uint4 a1 = ap[((wm * 2 + 1) * 2 + kc) * 32 + lane];
#pragma unroll
            for (int j = 0; j < 4; j++) {
                const uint4 b = bp[((kc * 2 + wn) * 4 + j) * 32 + lane];
                mma_tf32(acc[0][2 * j],     a0.x, a0.y, a0.z, a0.w, b.x, b.y);
                mma_tf32(acc[1][2 * j],     a1.x, a1.y, a1.z, a1.w, b.x, b.y);
                mma_tf32(acc[0][2 * j + 1], a0.x, a0.y, a0.z, a0.w, b.z, b.w);
                mma_tf32(acc[1][2 * j + 1], a1.x, a1.y, a1.z, a1.w, b.z, b.w);
            }
        }
        __syncthreads();

        if (it + GSTG < NIT) {
            const int kb = it + GSTG;
            const uint4* Ak = Asrc + (size_t)kb * astride;
            const uint4* Bk = Bsrc + (size_t)kb * bstride;
            uint4* d = sm4 + s * 1024;
            cpa16(&d[t],       Ak + t);
            cpa16(&d[t + 256], Ak + t + 256);
            cpa16(&d[t + 512], Bk + t);
            cpa16(&d[t + 768], Bk + t + 256);
        }
        cpa_commit();
    }

    // ---- epilogue ----
    if (mode == 2) {
#pragma unroll
        for (int tm = 0; tm < 2; tm++) {
#pragma unroll
            for (int rr = 0; rr < 2; rr++) {
                const int row = m0 + wm * 32 + tm * 16 + g + rr * 8;
#pragma unroll
                for (int tn = 0; tn < 8; tn++) {
                    const int col = n0 + wn * 64 + tn * 8 + 2 * q;
                    *(float2*)(C + (size_t)row * DMODEL + col) =
                        make_float2(acc[tm][tn][rr * 2], acc[tm][tn][rr * 2 + 1]);
                }
            }
        }
    } else {
        const int b  = m0 >> 11;
        const int sb = m0 & (S_LEN - 1);
        unsigned* base; bool rope;
        if (n0 < DMODEL) {
            base = g_q + (size_t)(b * NH + (n0 >> 7)) * S_LEN * HD; rope = true;
        } else if (n0 < DMODEL + KVDIM) {
            base = g_k + (size_t)(b * NKV + ((n0 - DMODEL) >> 7)) * S_LEN * HD; rope = true;
        } else {
            base = g_v + (size_t)(b * NKV + ((n0 - DMODEL - KVDIM) >> 7)) * S_LEN * HD; rope = false;
        }
#pragma unroll
        for (int tm = 0; tm < 2; tm++) {
#pragma unroll
            for (int rr = 0; rr < 2; rr++) {
                const int srow = sb + wm * 32 + tm * 16 + g + rr * 8;
#pragma unroll
                for (int tn = 0; tn < 8; tn++) {
                    const int cih = wn * 64 + tn * 8 + 2 * q;   // col within head
                    float re = acc[tm][tn][rr * 2 + 0];
                    float im = acc[tm][tn][rr * 2 + 1];
                    if (rope) {
                        const int j = cih >> 1;
                        const float c = cs[srow * 64 + j];
                        const float s = sn[srow * 64 + j];
                        const float r2 = re * c - im * s;
                        im = re * s + im * c;
                        re = r2;
                    }
                    uint2 u; u.x = f2tf(re); u.y = f2tf(im);
                    *(uint2*)(base + (size_t)srow * HD + cih) = u;
                }
            }
        }
    }
}

// ================= flash attention on tensor cores (tf32 mma) =====================
// BQ=128, BKV=64. 256 threads = 8 warps, each owns 16 q-rows.
// smem: Q[128][132] + 2 x { K[64][132] (reused as P[128][68]) , V[64][136] }.
// Epilogue writes g_attn in packed-A layout for the WO GEMM.
#define AQ_STR 132
#define AK_STR 132
#define AV_STR 136
#define AP_STR 68
#define KV_REG 8704
#define BUF_UINTS (KV_REG * 2)
#define Q_UINTS (128 * AQ_STR)
#define ATTN_SMEM ((Q_UINTS + 2 * BUF_UINTS) * 4)

__device__ __forceinline__ void attn_issue_kv(
    unsigned* sm, int t, int kt, int bi,
    const unsigned* kg, const unsigned* vg)
{
    unsigned* kb = sm + Q_UINTS + bi * BUF_UINTS;
    unsigned* vb = kb + KV_REG;
    const unsigned* ks = kg + (size_t)kt * 64 * HD;
    const unsigned* vs = vg + (size_t)kt * 64 * HD;
#pragma unroll
    for (int i = 0; i < 8; i++) {
        int c  = t + i * 256;
        int r  = c >> 5;
        int c4 = (c & 31) * 4;
        cpa16(&kb[r * AK_STR + c4], ks + (size_t)r * HD + c4);
        cpa16(&vb[r * AV_STR + c4], vs + (size_t)r * HD + c4);
    }
}

__global__ __launch_bounds__(256, 1) void attn_kernel()
{
    extern __shared__ unsigned sm[];
    unsigned* sQ = sm;

    const int t    = threadIdx.x;
    const int warp = t >> 5, lane = t & 31;
    const int g    = lane >> 2, q = lane & 3;
    const int qt   = blockIdx.x;
    const int bh   = blockIdx.y;
    const int b    = bh >> 5;
    const int h    = bh & 31;
    const int kvh  = h >> 2;

    const unsigned* qg = g_q + ((size_t)bh * S_LEN + qt * 128) * HD;
    const unsigned* kg = g_k + (size_t)(b * NKV + kvh) * S_LEN * HD;
    const unsigned* vg = g_v + (size_t)(b * NKV + kvh) * S_LEN * HD;

#pragma unroll
    for (int i = 0; i < 16; i++) {
        int c  = t + i * 256;
        int r  = c >> 5;
        int c4 = (c & 31) * 4;
        cpa16(&sQ[r * AQ_STR + c4], qg + (size_t)r * HD + c4);
    }
    attn_issue_kv(sm, t, 0, 0, kg, vg);
    cpa_commit();
    attn_issue_kv(sm, t, 1, 1, kg, vg);
    cpa_commit();

    const float scale = 0.08838834764831845f;

    float accO[16][4];
#pragma unroll
    for (int nf = 0; nf < 16; nf++)
#pragma unroll
        for (int r = 0; r < 4; r++) accO[nf][r] = 0.f;
    float m0v = -1e30f, m1v = -1e30f, l0 = 0.f, l1 = 0.f;

    const int aoffQ = (warp * 16 + g) * AQ_STR + q;

    for (int kt = 0; kt < S_LEN / 64; kt++) {
        unsigned* kb = sm + Q_UINTS + (kt & 1) * BUF_UINTS;
        unsigned* vb = kb + KV_REG;

        cpa_wait1();
        __syncthreads();

        float accS[8][4];
#pragma unroll
        for (int nf = 0; nf < 8; nf++)
#pragma unroll
            for (int r = 0; r < 4; r++) accS[nf][r] = 0.f;

#pragma unroll
        for (int kc = 0; kc < 128; kc += 8) {
            unsigned a0 = sQ[aoffQ + kc];
            unsigned a1 = sQ[aoffQ + kc + 8 * AQ_STR];
            unsigned a2 = sQ[aoffQ + kc + 4];
            unsigned a3 = sQ[aoffQ + kc + 8 * AQ_STR + 4];
#pragma unroll
            for (int nf = 0; nf < 8; nf++) {
                const int bo = (nf * 8 + g) * AK_STR + kc + q;
                mma_tf32(accS[nf], a0, a1, a2, a3, kb[bo], kb[bo + 4]);
            }
        }

        float al0, al1;
        {
            float mx = -1e30f;
#pragma unroll
            for (int nf = 0; nf < 8; nf++)
                mx = fmaxf(mx, fmaxf(accS[nf][0], accS[nf][1]));
            mx *= scale;
            mx = fmaxf(mx, __shfl_xor_sync(0xffffffffu, mx, 1));
            mx = fmaxf(mx, __shfl_xor_sync(0xffffffffu, mx, 2));
            float mn = fmaxf(m0v, mx);
            al0 = __expf(m0v - mn); m0v = mn;
            float s = 0.f;
#pragma unroll
            for (int nf = 0; nf < 8; nf++) {
                float p0 = __expf(accS[nf][0] * scale - mn);
                float p1 = __expf(accS[nf][1] * scale - mn);
                accS[nf][0] = p0; accS[nf][1] = p1; s += p0 + p1;
            }
            s += __shfl_xor_sync(0xffffffffu, s, 1);
            s += __shfl_xor_sync(0xffffffffu, s, 2);
            l0 = l0 * al0 + s;
        }
        {
            float mx = -1e30f;
#pragma unroll
            for (int nf = 0; nf < 8; nf++)
                mx = fmaxf(mx, fmaxf(accS[nf][2], accS[nf][3]));
            mx *= scale;
            mx = fmaxf(mx, __shfl_xor_sync(0xffffffffu, mx, 1));
            mx = fmaxf(mx, __shfl_xor_sync(0xffffffffu, mx, 2));
            float mn = fmaxf(m1v, mx);
            al1 = __expf(m1v - mn); m1v = mn;
            float s = 0.f;
#pragma unroll
            for (int nf = 0; nf < 8; nf++) {
                float p0 = __expf(accS[nf][2] * scale - mn);
                float p1 = __expf(accS[nf][3] * scale - mn);
                accS[nf][2] = p0; accS[nf][3] = p1; s += p0 + p1;
            }
            s += __shfl_xor_sync(0xffffffffu, s, 1);
            s += __shfl_xor_sync(0xffffffffu, s, 2);
            l1 = l1 * al1 + s;
        }

        __syncthreads();

        unsigned* sP = kb;
        const int pr = (warp * 16 + g) * AP_STR;
#pragma unroll
        for (int nf = 0; nf < 8; nf++) {
            uint2 u0; u0.x = f2tf(accS[nf][0]); u0.y = f2tf(accS[nf][1]);
            *(uint2*)&sP[pr + nf * 8 + 2 * q] = u0;
            uint2 u1; u1.x = f2tf(accS[nf][2]); u1.y = f2tf(accS[nf][3]);
            *(uint2*)&sP[pr + 8 * AP_STR + nf * 8 + 2 * q] = u1;
        }
#pragma unroll
        for (int nf = 0; nf < 16; nf++) {
            accO[nf][0] *= al0; accO[nf][1] *= al0;
            accO[nf][2] *= al1; accO[nf][3] *= al1;
        }
        __syncthreads();

        const int po = (warp * 16 + g) * AP_STR + q;
#pragma unroll
        for (int kc = 0; kc < 64; kc += 8) {
            unsigned a0 = sP[po + kc];
            unsigned a1 = sP[po + kc + 8 * AP_STR];
            unsigned a2 = sP[po + kc + 4];
            unsigned a3 = sP[po + kc + 8 * AP_STR + 4];
#pragma unroll
            for (int nf = 0; nf < 16; nf++) {
                const int bo = (kc + q) * AV_STR + nf * 8 + g;
                mma_tf32(accO[nf], a0, a1, a2, a3, vb[bo], vb[bo + 4 * AV_STR]);
            }
        }
        __syncthreads();

        if (kt + 2 < S_LEN / 64)
            attn_issue_kv(sm, t, kt + 2, kt & 1, kg, vg);
        cpa_commit();
    }
    cpa_wait0();

    // ---- normalize + write to g_attn in packed-A layout ----
    const float inv0 = 1.f / l0, inv1 = 1.f / l1;
    const int R0 = b * S_LEN + qt * 128 + warp * 16 + g;
#pragma unroll
    for (int nf = 0; nf < 16; nf++) {
        const int c = h * HD + nf * 8 + 2 * q;
        g_attn[packA_addr(R0,     c)]     = f2tf(accO[nf][0] * inv0);
        g_attn[packA_addr(R0,     c + 1)] = f2tf(accO[nf][1] * inv0);
        g_attn[packA_addr(R0 + 8, c)]     = f2tf(accO[nf][2] * inv1);
        g_attn[packA_addr(R0 + 8, c + 1)] = f2tf(accO[nf][3] * inv1);
    }
}

// ---------------- launch ---------------------------------------------------------
extern "C" void kernel_launch(void* const* d_in, const int* in_sizes, int n_in,
                              void* d_out, int out_size)
{
    const float* x  = (const float*)d_in[0];
    const float* cs = (const float*)d_in[1];
    const float* sn = (const float*)d_in[2];
    const float* wq = (const float*)d_in[3];
    const float* wk = (const float*)d_in[4];
    const float* wv = (const float*)d_in[5];
    const float* wo = (const float*)d_in[6];
    float* out = (float*)d_out;

    cudaFuncSetAttribute(attn_kernel, cudaFuncAttributeMaxDynamicSharedMemorySize, ATTN_SMEM);
    cudaFuncSetAttribute(gemm_pk,     cudaFuncAttributeMaxDynamicSharedMemorySize, GEMM_SMEM);

    // 0) pack x and weights into fragment layouts (tf32 bits)
    pack_x<<<dim3(DMODEL / 16, (B_SZ * S_LEN) / 128), 256>>>(x);
    pack_w<<<dim3(DMODEL / 128, DMODEL / 16), 256>>>(wq, 1, DMODEL);
    pack_w<<<dim3(KVDIM  / 128, DMODEL / 16), 256>>>(wk, 2, KVDIM);
    pack_w<<<dim3(KVDIM  / 128, DMODEL / 16), 256>>>(wv, 3, KVDIM);
    pack_w<<<dim3(DMODEL / 128, DMODEL / 16), 256>>>(wo, 4, DMODEL);

    // 1) fused QKV projection + RoPE-fused tf32 scatter
    gemm_pk<<<dim3((DMODEL + 2 * KVDIM) / 128, (B_SZ * S_LEN) / 128), 256, GEMM_SMEM>>>(
        1, nullptr, cs, sn);

    // 2) attention (legacy tf32 mma), writes packed g_attn
    attn_kernel<<<dim3(S_LEN / 128, B_SZ * NH), 256, ATTN_SMEM>>>();

    // 3) output projection
    gemm_pk<<<dim3(DMODEL / 128, (B_SZ * S_LEN) / 128), 256, GEMM_SMEM>>>(
        2, out, nullptr, nullptr);
}

// round 9
// speedup vs baseline: 13.3202x; 1.8544x over previous
#include <cuda_runtime.h>
#include <cuda_fp16.h>
#include <math.h>
#include <stdint.h>

#define S_LEN  2048
#define B_SZ   2
#define DMODEL 4096
#define KVDIM  1024
#define HD     128
#define NH     32
#define NKV    8

// ---------------- scratch (static device globals; no allocation) ----------------
// fragment-packed fp16 operands (uint = half2)
__device__ unsigned g_xp [(size_t)B_SZ * S_LEN * DMODEL / 2];   // x packed-A
__device__ unsigned g_wqp[(size_t)DMODEL * DMODEL / 2];          // wq packed-B
__device__ unsigned g_wkp[(size_t)DMODEL * KVDIM  / 2];          // wk packed-B
__device__ unsigned g_wvp[(size_t)DMODEL * KVDIM  / 2];          // wv packed-B
__device__ unsigned g_wop[(size_t)DMODEL * DMODEL / 2];          // wo packed-B
// intermediates
__device__ __half g_q [(size_t)B_SZ * NH  * S_LEN * HD];   // [b][h][s][d]
__device__ __half g_k [(size_t)B_SZ * NKV * S_LEN * HD];   // [b][g][s][d]
__device__ __half g_vT[(size_t)B_SZ * NKV * HD * S_LEN];   // [b][g][d][s]  (transposed)
__device__ unsigned g_attn[(size_t)B_SZ * S_LEN * DMODEL / 2];  // packed-A fp16

// Packed-A (M x K): stage = [kblk=k/16][mb=m/128] of 128x16 halfs = 256 uint4.
//   within: [mt(8)][lane(32)] -> uint4 slots {a0,a1,a2,a3}:
//   a0=(row mt*16+g, k 2q..2q+1) a1=(+8 row, same k) a2=(row, k 2q+8..9) a3=(+8,same)
// Packed-B (N x K): stage = [kblk][nb=n/128] of 128x16 halfs = 256 uint4.
//   within: [j(8 n16 tiles)][lane(32)] -> {b0 of n8#0, b1 of n8#0, b0 of n8#1, b1 of n8#1}
//   b0=(k 2q..2q+1, col j*16+g[+8]),  b1=(k 2q+8..9, same col)

// ---------------- helpers --------------------------------------------------------
__device__ __forceinline__ unsigned h2pack(float a, float b) {
    __half2 h = __floats2half2_rn(a, b);
    return *(unsigned*)&h;
}

__device__ __forceinline__ void mma_f16(float c[4],
    unsigned a0, unsigned a1, unsigned a2, unsigned a3,
    unsigned b0, unsigned b1)
{
    asm volatile(
        "mma.sync.aligned.m16n8k16.row.col.f32.f16.f16.f32 "
        "{%0,%1,%2,%3}, {%4,%5,%6,%7}, {%8,%9}, {%0,%1,%2,%3};"
        : "+f"(c[0]), "+f"(c[1]), "+f"(c[2]), "+f"(c[3])
        : "r"(a0), "r"(a1), "r"(a2), "r"(a3), "r"(b0), "r"(b1));
}

__device__ __forceinline__ void cpa16(void* smem_dst, const void* gsrc) {
    unsigned s = (unsigned)__cvta_generic_to_shared(smem_dst);
    asm volatile("cp.async.cg.shared.global [%0], [%1], 16;" :: "r"(s), "l"(gsrc));
}
__device__ __forceinline__ void cpa_commit() {
    asm volatile("cp.async.commit_group;" ::: "memory");
}
__device__ __forceinline__ void cpa_wait1() {
    asm volatile("cp.async.wait_group 1;" ::: "memory");
}
__device__ __forceinline__ void cpa_wait3() {
    asm volatile("cp.async.wait_group 3;" ::: "memory");
}
__device__ __forceinline__ void cpa_wait0() {
    asm volatile("cp.async.wait_group 0;" ::: "memory");
}

// ---------------- pre-pass: pack x and weights into fp16 fragment layouts --------
__global__ __launch_bounds__(256) void pack_x(const float* __restrict__ x)
{
    const int kblk = blockIdx.x;      // 0..255
    const int mb   = blockIdx.y;      // 0..31
    uint4* dst = (uint4*)g_xp + ((size_t)kblk * 32 + mb) * 256;
    const int id = threadIdx.x;
    const int mt = id >> 5, lane = id & 31;
    const int g = lane >> 2, q = lane & 3;
    const int r = mb * 128 + mt * 16 + g;
    const int c = kblk * 16 + 2 * q;
    const float* x0 = x + (size_t)r * DMODEL + c;
    const float* x8 = x0 + (size_t)8 * DMODEL;
    uint4 u;
    u.x = h2pack(x0[0], x0[1]);
    u.y = h2pack(x8[0], x8[1]);
    u.z = h2pack(x0[8], x0[9]);
    u.w = h2pack(x8[8], x8[9]);
    dst[id] = u;
}

// src [K][N] fp32 row-major -> packed-B fp16.  grid (N/128, K/16), 256 threads.
__global__ __launch_bounds__(256) void pack_w(const float* __restrict__ src,
                                              int which, int N)
{
    unsigned* dsel = (which == 1) ? g_wqp
                   : (which == 2) ? g_wkp
                   : (which == 3) ? g_wvp
                                  : g_wop;
    const int nb = blockIdx.x, kblk = blockIdx.y;
    uint4* dst = (uint4*)dsel + ((size_t)kblk * (N / 128) + nb) * 256;
    const int id = threadIdx.x;
    const int j = id >> 5, lane = id & 31;
    const int g = lane >> 2, q = lane & 3;
    const int k = kblk * 16 + 2 * q;
    const int n = nb * 128 + j * 16 + g;
    const float* s0 = src + (size_t)k * N + n;
    uint4 u;
    u.x = h2pack(s0[0],                    s0[(size_t)N]);
    u.y = h2pack(s0[(size_t)8 * N],        s0[(size_t)9 * N]);
    u.z = h2pack(s0[8],                    s0[(size_t)N + 8]);
    u.w = h2pack(s0[(size_t)8 * N + 8],    s0[(size_t)9 * N + 8]);
    dst[id] = u;
}

// ================= legacy-mma FP16 GEMM on fragment-packed operands ==============
// 128x128 CTA tile, BK=32 (2 kblks/stage), 256 threads = 8 warps (4m x 2n),
// warp tile 32x64. 4-stage cp.async pipeline, stage = 8KB A + 8KB B.
// mode 1: A=g_xp, B={g_wqp|g_wkp|g_wvp}; epilogue RoPE + half scatter (V transposed).
// mode 2: A=g_attn (packed), B=g_wop; fp32 row-major store to C.
#define GSTG 4
#define GEMM_SMEM (GSTG * 16384)

__global__ __launch_bounds__(256, 2) void gemm_pk(
    int mode, float* __restrict__ C,
    const float* __restrict__ cs, const float* __restrict__ sn)
{
    extern __shared__ uint4 sm4[];

    const int t    = threadIdx.x;
    const int warp = t >> 5, lane = t & 31;
    const int wm   = warp >> 1, wn = warp & 1;
    const int g    = lane >> 2, q = lane & 3;
    const int m0   = blockIdx.y * 128;
    const int n0   = blockIdx.x * 128;
    const int mb   = blockIdx.y;

    const uint4* Asrc = ((mode == 2) ? (const uint4*)g_attn : (const uint4*)g_xp)
                        + (size_t)mb * 256;
    const size_t astride = 32 * 256;          // uint4 per kblk

    const uint4* Bsrc; size_t bstride;
    if (mode == 2) {
        Bsrc = (const uint4*)g_wop + (size_t)(n0 >> 7) * 256;                bstride = 32 * 256;
    } else if (n0 < DMODEL) {
        Bsrc = (const uint4*)g_wqp + (size_t)(n0 >> 7) * 256;                bstride = 32 * 256;
    } else if (n0 < DMODEL + KVDIM) {
        Bsrc = (const uint4*)g_wkp + (size_t)((n0 - DMODEL) >> 7) * 256;     bstride = 8 * 256;
    } else {
        Bsrc = (const uint4*)g_wvp + (size_t)((n0 - DMODEL - KVDIM) >> 7) * 256; bstride = 8 * 256;
    }

    float acc[2][8][4];
#pragma unroll
    for (int i = 0; i < 2; i++)
#pragma unroll
        for (int j = 0; j < 8; j++)
#pragma unroll
            for (int r = 0; r < 4; r++) acc[i][j][r] = 0.f;

#define LOAD_STAGE(st, kb2)                                                      \
    do {                                                                         \
        uint4* d = sm4 + (st) * 1024;                                            \
        _Pragma("unroll")                                                        \
        for (int kh = 0; kh < 2; kh++) {                                         \
            const uint4* Ak = Asrc + (size_t)((kb2) + kh) * astride;             \
            const uint4* Bk = Bsrc + (size_t)((kb2) + kh) * bstride;             \
            cpa16(&d[kh * 512 + t],       Ak + t);                               \
            cpa16(&d[kh * 512 + 256 + t], Bk + t);                               \
        }                                                                        \
    } while (0)

#pragma unroll
    for (int st = 0; st < GSTG; st++) {
        LOAD_STAGE(st, st * 2);
        cpa_commit();
    }

    const int NIT = DMODEL / 32;   // 128
    for (int it = 0; it < NIT; it++) {
        const int s = it & 3;
        cpa_wait3();
        __syncthreads();

#pragma unroll
        for (int kh = 0; kh < 2; kh++) {
            const uint4* ap = sm4 + s * 1024 + kh * 512;
            const uint4* bp = ap + 256;
            const uint4 a0 = ap[(wm * 2 + 0) * 32 + lane];
            const uint4 a1 = ap[(wm * 2 + 1) * 32 + lane];
#pragma unroll
            for (int j = 0; j < 4; j++) {
                const uint4 b = bp[(wn * 4 + j) * 32 + lane];
                mma_f16(acc[0][2 * j],     a0.x, a0.y, a0.z, a0.w, b.x, b.y);
                mma_f16(acc[1][2 * j],     a1.x, a1.y, a1.z, a1.w, b.x, b.y);
                mma_f16(acc[0][2 * j + 1], a0.x, a0.y, a0.z, a0.w, b.z, b.w);
                mma_f16(acc[1][2 * j + 1], a1.x, a1.y, a1.z, a1.w, b.z, b.w);
            }
        }
        __syncthreads();

        if (it + GSTG < NIT) LOAD_STAGE(s, (it + GSTG) * 2);
        cpa_commit();
    }

    // ---- epilogue ----
    if (mode == 2) {
#pragma unroll
        for (int tm = 0; tm < 2; tm++) {
#pragma unroll
            for (int rr = 0; rr < 2; rr++) {
                const int row = m0 + wm * 32 + tm * 16 + g + rr * 8;
#pragma unroll
                for (int tn = 0; tn < 8; tn++) {
                    const int col = n0 + wn * 64 + tn * 8 + 2 * q;
                    *(float2*)(C + (size_t)row * DMODEL + col) =
                        make_float2(acc[tm][tn][rr * 2], acc[tm][tn][rr * 2 + 1]);
                }
            }
        }
    } else {
        const int b  = m0 >> 11;
        const int sb = m0 & (S_LEN - 1);
        const bool isQ = (n0 < DMODEL);
        const bool isK = (!isQ) && (n0 < DMODEL + KVDIM);
        __half* base;
        if (isQ)      base = g_q  + (size_t)(b * NH  + (n0 >> 7)) * S_LEN * HD;
        else if (isK) base = g_k  + (size_t)(b * NKV + ((n0 - DMODEL) >> 7)) * S_LEN * HD;
        else          base = g_vT + (size_t)(b * NKV + ((n0 - DMODEL - KVDIM) >> 7)) * HD * S_LEN;
#pragma unroll
        for (int tm = 0; tm < 2; tm++) {
#pragma unroll
            for (int rr = 0; rr < 2; rr++) {
                const int srow = sb + wm * 32 + tm * 16 + g + rr * 8;
#pragma unroll
                for (int tn = 0; tn < 8; tn++) {
                    const int cih = wn * 64 + tn * 8 + 2 * q;   // col within head
                    float re = acc[tm][tn][rr * 2 + 0];
                    float im = acc[tm][tn][rr * 2 + 1];
                    if (isQ || isK) {
                        const int j = cih >> 1;
                        const float c = cs[srow * 64 + j];
                        const float s = sn[srow * 64 + j];
                        const float r2 = re * c - im * s;
                        im = re * s + im * c;
                        re = r2;
                        *(unsigned*)(base + (size_t)srow * HD + cih) = h2pack(re, im);
                    } else {
                        // V transposed: [d][s]
                        base[(size_t)cih * S_LEN + srow]       = __float2half_rn(re);
                        base[(size_t)(cih + 1) * S_LEN + srow] = __float2half_rn(im);
                    }
                }
            }
        }
    }
}

// ================= flash attention, fp16 m16n8k16 =================================
// BQ=128, BKV=64. 256 threads = 8 warps, warp w owns q-rows w*16..w*16+15.
// smem (halfs): Q[128][136] | 2 x { K[64][136], VT[128][72] } | P[128][72]
#define QSTR 136
#define KSTR 136
#define VSTR 72
#define PSTR 72
#define Q_H     (128 * QSTR)          // 17408
#define KREG_H  (64 * KSTR)           // 8704
#define VREG_H  (128 * VSTR)          // 9216
#define STAGE_H (KREG_H + VREG_H)     // 17920
#define P_OFF_H (Q_H + 2 * STAGE_H)   // 53248
#define ATTN_SMEM ((P_OFF_H + 128 * PSTR) * 2)   // 124928 bytes

__device__ __forceinline__ void attn_issue_kv(
    __half* smh, int t, int kt, int bi,
    const __half* kg, const __half* vg)
{
    __half* kb = smh + Q_H + bi * STAGE_H;
    __half* vt = kb + KREG_H;
    const __half* ks = kg + (size_t)kt * 64 * HD;
#pragma unroll
    for (int i = 0; i < 4; i++) {
        const int id = t + i * 256;            // 0..1023
        const int r = id >> 4, c = id & 15;    // K: 64 rows x 16 chunks
        cpa16(&kb[r * KSTR + c * 8], ks + (size_t)r * HD + c * 8);
    }
#pragma unroll
    for (int i = 0; i < 4; i++) {
        const int id = t + i * 256;
        const int d = id >> 3, c = id & 7;     // VT: 128 rows x 8 chunks
        cpa16(&vt[d * VSTR + c * 8], vg + (size_t)d * S_LEN + kt * 64 + c * 8);
    }
}

__global__ __launch_bounds__(256, 1) void attn_kernel()
{
    extern __shared__ __half smh[];
    __half* sQ = smh;
    __half* sP = smh + P_OFF_H;

    const int t    = threadIdx.x;
    const int warp = t >> 5, lane = t & 31;
    const int g    = lane >> 2, q = lane & 3;
    const int qt   = blockIdx.x;          // 0..15
    const int bh   = blockIdx.y;          // 0..63
    const int b    = bh >> 5;
    const int h    = bh & 31;
    const int kvh  = h >> 2;

    const __half* qg = g_q  + ((size_t)bh * S_LEN + qt * 128) * HD;
    const __half* kg = g_k  + (size_t)(b * NKV + kvh) * S_LEN * HD;
    const __half* vg = g_vT + (size_t)(b * NKV + kvh) * HD * S_LEN;

    // prologue: Q + stage0 (group 0), stage1 (group 1)
#pragma unroll
    for (int i = 0; i < 8; i++) {
        const int id = t + i * 256;            // 0..2047
        const int r = id >> 4, c = id & 15;
        cpa16(&sQ[r * QSTR + c * 8], qg + (size_t)r * HD + c * 8);
    }
    attn_issue_kv(smh, t, 0, 0, kg, vg);
    cpa_commit();
    attn_issue_kv(smh, t, 1, 1, kg, vg);
    cpa_commit();

    const float scale = 0.08838834764831845f;   // 1/sqrt(128)

    float accO[16][4];
#pragma unroll
    for (int nf = 0; nf < 16; nf++)
#pragma unroll
        for (int r = 0; r < 4; r++) accO[nf][r] = 0.f;
    float m0v = -1e30f, m1v = -1e30f, l0 = 0.f, l1 = 0.f;

    const int qoff = (warp * 16 + g) * QSTR;
    const int poff = (warp * 16 + g) * PSTR;

    for (int kt = 0; kt < S_LEN / 64; kt++) {
        __half* kb = smh + Q_H + (kt & 1) * STAGE_H;
        __half* vt = kb + KREG_H;

        cpa_wait1();
        __syncthreads();

        // ---- S = Q K^T ----
        float accS[8][4];
#pragma unroll
        for (int nf = 0; nf < 8; nf++)
#pragma unroll
            for (int r = 0; r < 4; r++) accS[nf][r] = 0.f;

#pragma unroll
        for (int kc = 0; kc < 128; kc += 16) {
            const unsigned a0 = *(const unsigned*)&sQ[qoff + kc + 2 * q];
            const unsigned a1 = *(const unsigned*)&sQ[qoff + 8 * QSTR + kc + 2 * q];
            const unsigned a2 = *(const unsigned*)&sQ[qoff + kc + 2 * q + 8];
            const unsigned a3 = *(const unsigned*)&sQ[qoff + 8 * QSTR + kc + 2 * q + 8];
#pragma unroll
            for (int nf = 0; nf < 8; nf++) {
                const int ko = (nf * 8 + g) * KSTR + kc + 2 * q;
                mma_f16(accS[nf], a0, a1, a2, a3,
                        *(const unsigned*)&kb[ko], *(const unsigned*)&kb[ko + 8]);
            }
        }

        // ---- online softmax (rows g and g+8) ----
        float al0, al1;
        {
            float mx = -1e30f;
#pragma unroll
            for (int nf = 0; nf < 8; nf++)
                mx = fmaxf(mx, fmaxf(accS[nf][0], accS[nf][1]));
            mx *= scale;
            mx = fmaxf(mx, __shfl_xor_sync(0xffffffffu, mx, 1));
            mx = fmaxf(mx, __shfl_xor_sync(0xffffffffu, mx, 2));
            float mn = fmaxf(m0v, mx);
            al0 = __expf(m0v - mn); m0v = mn;
            float s = 0.f;
#pragma unroll
            for (int nf = 0; nf < 8; nf++) {
                float p0 = __expf(accS[nf][0] * scale - mn);
                float p1 = __expf(accS[nf][1] * scale - mn);
                accS[nf][0] = p0; accS[nf][1] = p1; s += p0 + p1;
            }
            s += __shfl_xor_sync(0xffffffffu, s, 1);
            s += __shfl_xor_sync(0xffffffffu, s, 2);
            l0 = l0 * al0 + s;
        }
        {
            float mx = -1e30f;
#pragma unroll
            for (int nf = 0; nf < 8; nf++)
                mx = fmaxf(mx, fmaxf(accS[nf][2], accS[nf][3]));
            mx *= scale;
            mx = fmaxf(mx, __shfl_xor_sync(0xffffffffu, mx, 1));
            mx = fmaxf(mx, __shfl_xor_sync(0xffffffffu, mx, 2));
            float mn = fmaxf(m1v, mx);
            al1 = __expf(m1v - mn); m1v = mn;
            float s = 0.f;
#pragma unroll
            for (int nf = 0; nf < 8; nf++) {
                float p0 = __expf(accS[nf][2] * scale - mn);
                float p1 = __expf(accS[nf][3] * scale - mn);
                accS[nf][2] = p0; accS[nf][3] = p1; s += p0 + p1;
            }
            s += __shfl_xor_sync(0xffffffffu, s, 1);
            s += __shfl_xor_sync(0xffffffffu, s, 2);
            l1 = l1 * al1 + s;
        }

        // ---- store P (fp16) — warp-local buffer, warp-sync only ----
#pragma unroll
        for (int nf = 0; nf < 8; nf++) {
            *(unsigned*)&sP[poff + nf * 8 + 2 * q]            = h2pack(accS[nf][0], accS[nf][1]);
            *(unsigned*)&sP[poff + 8 * PSTR + nf * 8 + 2 * q] = h2pack(accS[nf][2], accS[nf][3]);
        }
#pragma unroll
        for (int nf = 0; nf < 16; nf++) {
            accO[nf][0] *= al0; accO[nf][1] *= al0;
            accO[nf][2] *= al1; accO[nf][3] *= al1;
        }
        __syncwarp();

        // ---- O += P V  (B from transposed V tile) ----
#pragma unroll
        for (int kc = 0; kc < 64; kc += 16) {
            const unsigned a0 = *(const unsigned*)&sP[poff + kc + 2 * q];
            const unsigned a1 = *(const unsigned*)&sP[poff + 8 * PSTR + kc + 2 * q];
            const unsigned a2 = *(const unsigned*)&sP[poff + kc + 2 * q + 8];
            const unsigned a3 = *(const unsigned*)&sP[poff + 8 * PSTR + kc + 2 * q + 8];
#pragma unroll
            for (int nf = 0; nf < 16; nf++) {
                const int vo = (nf * 8 + g) * VSTR + kc + 2 * q;
                mma_f16(accO[nf], a0, a1, a2, a3,
                        *(const unsigned*)&vt[vo], *(const unsigned*)&vt[vo + 8]);
            }
        }
        __syncthreads();   // stage fully consumed

        if (kt + 2 < S_LEN / 64)
            attn_issue_kv(smh, t, kt + 2, kt & 1, kg, vg);
        cpa_commit();
    }
    cpa_wait0();

    // ---- normalize + write g_attn in packed-A fp16 layout ----
    const float inv0 = 1.f / l0, inv1 = 1.f / l1;
    const int mbA = b * (S_LEN / 128) + qt;     // global M-block
#pragma unroll
    for (int nf = 0; nf < 16; nf++) {
        const int kblk = h * 8 + (nf >> 1);
        const size_t off = ((size_t)(kblk * 32 + mbA) * 256 + warp * 32 + lane) * 4
                         + (nf & 1) * 2;
        uint2 u;
        u.x = h2pack(accO[nf][0] * inv0, accO[nf][1] * inv0);
        u.y = h2pack(accO[nf][2] * inv1, accO[nf][3] * inv1);
        *(uint2*)&g_attn[off] = u;
    }
}

// ---------------- launch ---------------------------------------------------------
extern "C" void kernel_launch(void* const* d_in, const int* in_sizes, int n_in,
                              void* d_out, int out_size)
{
    const float* x  = (const float*)d_in[0];
    const float* cs = (const float*)d_in[1];
    const float* sn = (const float*)d_in[2];
    const float* wq = (const float*)d_in[3];
    const float* wk = (const float*)d_in[4];
    const float* wv = (const float*)d_in[5];
    const float* wo = (const float*)d_in[6];
    float* out = (float*)d_out;

    cudaFuncSetAttribute(attn_kernel, cudaFuncAttributeMaxDynamicSharedMemorySize, ATTN_SMEM);
    cudaFuncSetAttribute(gemm_pk,     cudaFuncAttributeMaxDynamicSharedMemorySize, GEMM_SMEM);

    // 0) pack x and weights into fp16 fragment layouts
    pack_x<<<dim3(DMODEL / 16, (B_SZ * S_LEN) / 128), 256>>>(x);
    pack_w<<<dim3(DMODEL / 128, DMODEL / 16), 256>>>(wq, 1, DMODEL);
    pack_w<<<dim3(KVDIM  / 128, DMODEL / 16), 256>>>(wk, 2, KVDIM);
    pack_w<<<dim3(KVDIM  / 128, DMODEL / 16), 256>>>(wv, 3, KVDIM);
    pack_w<<<dim3(DMODEL / 128, DMODEL / 16), 256>>>(wo, 4, DMODEL);

    // 1) fused QKV projection + RoPE epilogue (V stored transposed)
    gemm_pk<<<dim3((DMODEL + 2 * KVDIM) / 128, (B_SZ * S_LEN) / 128), 256, GEMM_SMEM>>>(
        1, nullptr, cs, sn);

    // 2) attention (fp16 mma), writes packed g_attn
    attn_kernel<<<dim3(S_LEN / 128, B_SZ * NH), 256, ATTN_SMEM>>>();

    // 3) output projection
    gemm_pk<<<dim3(DMODEL / 128, (B_SZ * S_LEN) / 128), 256, GEMM_SMEM>>>(
        2, out, nullptr, nullptr);
}